// round 9
// baseline (speedup 1.0000x reference)
#include <cuda_runtime.h>
#include <cuda_bf16.h>
#include <cuda_fp16.h>

#define NN 50000
#define NE 800000
#define DD 128
#define NL 3
#define NG 256
#define NCLS 10
#define M_TILES 391   // ceil(50000/128)

// chunking for agg/gemm0 pipeline (4 chunks, tile-aligned)
#define NCH 4
static const int CH_TILE0[NCH] = {0, 98, 196, 294};
static const int CH_TILES[NCH] = {98, 98, 98, 97};
static const int CH_NODE0[NCH] = {0, 12544, 25088, 37632};
static const int CH_NODES[NCH] = {12544, 12544, 12544, 12368};

// ---------------- scratch (static device globals; no allocation) ----------------
__device__ unsigned short d_Hb[NN * DD];     // h as fp16 (gather format)
__device__ float d_B[NN * DD];               // agg (fp32), then z2
__device__ float d_C[NN * DD];               // z1
__device__ float d_stats[NL * 2 * 2 * DD];   // per (layer, bn#): [sum | sumsq]
__device__ float d_readout[NG * NL * DD];
__device__ unsigned short d_Wt[6 * 2 * DD * DD];  // [mat][hi/lo][n][k] bf16
__device__ int   d_deg[NN];
__device__ int   d_cur[NN];
__device__ int   d_off[NN + 1];
__device__ int   d_csr[NE];
__device__ int   d_bsum[256];
__device__ int   d_is64;

// ---------------- helpers ----------------
__device__ __forceinline__ void red4(float* p, float4 v) {
    asm volatile("red.global.add.v4.f32 [%0], {%1,%2,%3,%4};"
                 :: "l"(p), "f"(v.x), "f"(v.y), "f"(v.z), "f"(v.w) : "memory");
}
__device__ __forceinline__ unsigned smem_u32(const void* p) {
    unsigned r;
    asm("{ .reg .u64 t; cvta.to.shared.u64 t, %1; cvt.u32.u64 %0, t; }" : "=r"(r) : "l"(p));
    return r;
}
__device__ __forceinline__ void cpasync16(unsigned dst, const void* src) {
    asm volatile("cp.async.cg.shared.global [%0], [%1], 16;" :: "r"(dst), "l"(src));
}
__device__ __forceinline__ void mma16816(float* d, const unsigned* a, const unsigned* b) {
    asm volatile("mma.sync.aligned.m16n8k16.row.col.f32.bf16.bf16.f32 "
                 "{%0,%1,%2,%3},{%4,%5,%6,%7},{%8,%9},{%0,%1,%2,%3};"
                 : "+f"(d[0]), "+f"(d[1]), "+f"(d[2]), "+f"(d[3])
                 : "r"(a[0]), "r"(a[1]), "r"(a[2]), "r"(a[3]), "r"(b[0]), "r"(b[1]));
}
__device__ __forceinline__ void ldsm4(unsigned* r, unsigned addr) {
    asm volatile("ldmatrix.sync.aligned.m8n8.x4.shared.b16 {%0,%1,%2,%3},[%4];"
                 : "=r"(r[0]), "=r"(r[1]), "=r"(r[2]), "=r"(r[3]) : "r"(addr));
}
__device__ __forceinline__ void bsplit2(float x, float y, unsigned& hi, unsigned& lo) {
    __nv_bfloat162 h = __floats2bfloat162_rn(x, y);
    float rx = x - __bfloat162float(h.x);
    float ry = y - __bfloat162float(h.y);
    __nv_bfloat162 l = __floats2bfloat162_rn(rx, ry);
    hi = *(unsigned*)&h;
    lo = *(unsigned*)&l;
}
__device__ __forceinline__ float2 h2f(unsigned u) {
    return __half22float2(*(__half2*)&u);
}
__device__ __forceinline__ uint2 f4_to_h4(float4 v) {
    __half2 a = __floats2half2_rn(v.x, v.y);
    __half2 b = __floats2half2_rn(v.z, v.w);
    uint2 o; o.x = *(unsigned*)&a; o.y = *(unsigned*)&b;
    return o;
}
__device__ __forceinline__ void addrow(float4& a, uint2 v) {
    float2 p0 = h2f(v.x), p1 = h2f(v.y);
    a.x += p0.x; a.y += p0.y; a.z += p1.x; a.w += p1.y;
}

// ---------------- setup kernels ----------------

__global__ void k_init(const int* __restrict__ ei) {
    int i = blockIdx.x * 256 + threadIdx.x;
    if (i == 0) {
        int z = 1;
#pragma unroll
        for (int k = 1; k < 256; k += 2) z &= (ei[k] == 0);
        d_is64 = z;
    }
    if (i < NG * NL * DD) d_readout[i] = 0.f;
    if (i < NL * 2 * 2 * DD) d_stats[i] = 0.f;
    if (i < NN) d_deg[i] = 0;
}

__global__ void k_prep(const float* __restrict__ x,
                       const float* __restrict__ W1, const float* __restrict__ W2) {
    if (blockIdx.x < 6250) {
        int i = blockIdx.x * 256 + threadIdx.x;      // NN*32 = 1.6M
        float4 v = ((const float4*)x)[i];
        ((uint2*)d_Hb)[i] = f4_to_h4(v);
    } else {
        int id = (blockIdx.x - 6250) * 256 + threadIdx.x;  // 6*16384
        int mat = id >> 14;
        int r = id & 16383;
        int n = r & 127, k = r >> 7;
        const float* src = (mat < 3) ? (W1 + mat * 16384) : (W2 + (mat - 3) * 16384);
        float v = src[k * DD + n];
        __nv_bfloat16 hb = __float2bfloat16_rn(v);
        float lof = v - __bfloat162float(hb);
        __nv_bfloat16 lb = __float2bfloat16_rn(lof);
        int base = mat * 32768;
        d_Wt[base + n * DD + k] = __bfloat16_as_ushort(hb);
        d_Wt[base + 16384 + n * DD + k] = __bfloat16_as_ushort(lb);
    }
}

__global__ void k_hist(const int* __restrict__ ei) {
    int e = blockIdx.x * 256 + threadIdx.x;
    if (e >= NE) return;
    int dst = d_is64 ? ei[2 * (NE + e)] : ei[NE + e];
    atomicAdd(&d_deg[dst], 1);
}

__global__ void k_scan1() {
    __shared__ int s[256];
    int t = threadIdx.x;
    int i = blockIdx.x * 256 + t;
    int v = (i < NN) ? d_deg[i] : 0;
    s[t] = v;
    __syncthreads();
#pragma unroll
    for (int d = 1; d < 256; d <<= 1) {
        int x = (t >= d) ? s[t - d] : 0;
        __syncthreads();
        s[t] += x;
        __syncthreads();
    }
    if (i < NN) d_off[i + 1] = s[t];
    if (t == 255) d_bsum[blockIdx.x] = s[255];
}

__global__ void k_scan23() {
    __shared__ int s[256];
    int t = threadIdx.x;
    s[t] = (t < 196) ? d_bsum[t] : 0;
    __syncthreads();
#pragma unroll
    for (int d = 1; d < 256; d <<= 1) {
        int x = (t >= d) ? s[t - d] : 0;
        __syncthreads();
        s[t] += x;
        __syncthreads();
    }
    int b = blockIdx.x;
    int pre = (b == 0) ? 0 : s[b - 1];
    int i = b * 256 + t;
    if (i < NN) { d_off[i + 1] += pre; d_cur[i] = 0; }
    if (i == 0) d_off[0] = 0;
}

__global__ void k_fill(const int* __restrict__ ei) {
    int e = blockIdx.x * 256 + threadIdx.x;
    if (e >= NE) return;
    int src, dst;
    if (d_is64) { src = ei[2 * e]; dst = ei[2 * (NE + e)]; }
    else        { src = ei[e];     dst = ei[NE + e]; }
    int p = atomicAdd(&d_cur[dst], 1);
    d_csr[d_off[dst] + p] = src;
}

// One warp per TWO nodes of [node0, node0+ncount): full-warp uint2 gather.
__global__ void k_agg(int node0, int ncount) {
    int w = (blockIdx.x * 256 + threadIdx.x) >> 5;
    if (2 * w >= ncount) return;
    int n0 = node0 + 2 * w, n1 = n0 + 1;
    int lane = threadIdx.x & 31;
    const uint2* hv = (const uint2*)d_Hb;   // 32 uint2 per node row
    float4 aA, aB;
    { uint2 v = __ldg(&hv[(long)n0 * 32 + lane]); float2 p0 = h2f(v.x), p1 = h2f(v.y);
      aA = make_float4(p0.x, p0.y, p1.x, p1.y); }
    { uint2 v = __ldg(&hv[(long)n1 * 32 + lane]); float2 p0 = h2f(v.x), p1 = h2f(v.y);
      aB = make_float4(p0.x, p0.y, p1.x, p1.y); }
    int j0 = d_off[n0], e0 = d_off[n0 + 1];
    int j1 = e0,        e1 = d_off[n1 + 1];
    while (j0 + 4 <= e0 && j1 + 4 <= e1) {
        int s00 = d_csr[j0], s01 = d_csr[j0 + 1], s02 = d_csr[j0 + 2], s03 = d_csr[j0 + 3];
        int s10 = d_csr[j1], s11 = d_csr[j1 + 1], s12 = d_csr[j1 + 2], s13 = d_csr[j1 + 3];
        uint2 v00 = __ldg(&hv[(long)s00 * 32 + lane]);
        uint2 v01 = __ldg(&hv[(long)s01 * 32 + lane]);
        uint2 v02 = __ldg(&hv[(long)s02 * 32 + lane]);
        uint2 v03 = __ldg(&hv[(long)s03 * 32 + lane]);
        uint2 v10 = __ldg(&hv[(long)s10 * 32 + lane]);
        uint2 v11 = __ldg(&hv[(long)s11 * 32 + lane]);
        uint2 v12 = __ldg(&hv[(long)s12 * 32 + lane]);
        uint2 v13 = __ldg(&hv[(long)s13 * 32 + lane]);
        addrow(aA, v00); addrow(aA, v01); addrow(aA, v02); addrow(aA, v03);
        addrow(aB, v10); addrow(aB, v11); addrow(aB, v12); addrow(aB, v13);
        j0 += 4; j1 += 4;
    }
    for (; j0 + 4 <= e0; j0 += 4) {
        int s0 = d_csr[j0], s1 = d_csr[j0 + 1], s2 = d_csr[j0 + 2], s3 = d_csr[j0 + 3];
        uint2 v0 = __ldg(&hv[(long)s0 * 32 + lane]);
        uint2 v1 = __ldg(&hv[(long)s1 * 32 + lane]);
        uint2 v2 = __ldg(&hv[(long)s2 * 32 + lane]);
        uint2 v3 = __ldg(&hv[(long)s3 * 32 + lane]);
        addrow(aA, v0); addrow(aA, v1); addrow(aA, v2); addrow(aA, v3);
    }
    for (; j0 < e0; j0++) addrow(aA, __ldg(&hv[(long)d_csr[j0] * 32 + lane]));
    for (; j1 + 4 <= e1; j1 += 4) {
        int s0 = d_csr[j1], s1 = d_csr[j1 + 1], s2 = d_csr[j1 + 2], s3 = d_csr[j1 + 3];
        uint2 v0 = __ldg(&hv[(long)s0 * 32 + lane]);
        uint2 v1 = __ldg(&hv[(long)s1 * 32 + lane]);
        uint2 v2 = __ldg(&hv[(long)s2 * 32 + lane]);
        uint2 v3 = __ldg(&hv[(long)s3 * 32 + lane]);
        addrow(aB, v0); addrow(aB, v1); addrow(aB, v2); addrow(aB, v3);
    }
    for (; j1 < e1; j1++) addrow(aB, __ldg(&hv[(long)d_csr[j1] * 32 + lane]));
    ((float4*)d_B)[(long)n0 * 32 + lane] = aA;
    ((float4*)d_B)[(long)n1 * 32 + lane] = aB;
}

// ---------------- tensor-core GEMM (bf16-split, fp32-accurate) ----------------
// Processes tiles [tile0, tile0+gridDim.x).
template <int MODE>
__global__ void __launch_bounds__(256, 2)
k_gemm(int tile0,
       const float* __restrict__ P, const unsigned short* __restrict__ Wt,
       const float* __restrict__ bias,
       const float* __restrict__ g, const float* __restrict__ bt,
       const float* __restrict__ statsIn, float* __restrict__ statsOut,
       float* __restrict__ out) {
    __shared__ __align__(16) unsigned char sm[40960];
    unsigned sbase = smem_u32(sm);
    const unsigned ALO = 10240, WHI = 20480;

    int t = threadIdx.x;
    int lane = t & 31, wid = t >> 5;
    int wm = wid & 3, wn = wid >> 2;
    int m0w = wm * 32, n0w = wn * 64;
    int row0 = (tile0 + blockIdx.x) * 128;
    int kc = (t & 7) << 2;

#pragma unroll
    for (int i = 0; i < 4; i++) {
        int id = t + i * 256;
        int plane = id >> 9, n = (id >> 2) & 127, q = id & 3;
        cpasync16(sbase + WHI + plane * 10240 + n * 80 + q * 16,
                  Wt + plane * 16384 + n * DD + q * 8);
    }
    asm volatile("cp.async.commit_group;");

    float4 pa[4];
#pragma unroll
    for (int i = 0; i < 4; i++) {
        int row = (t + i * 256) >> 3;
        int gr = row0 + row;
        pa[i] = (gr < NN) ? *(const float4*)(P + (long)gr * DD + kc)
                          : make_float4(0.f, 0.f, 0.f, 0.f);
    }

    float acc[2][8][4];
#pragma unroll
    for (int ni = 0; ni < 8; ni++) {
        int c0 = n0w + 8 * ni + 2 * (lane & 3);
        float b0 = bias[c0], b1 = bias[c0 + 1];
#pragma unroll
        for (int mi = 0; mi < 2; mi++) {
            acc[mi][ni][0] = b0; acc[mi][ni][1] = b1;
            acc[mi][ni][2] = b0; acc[mi][ni][3] = b1;
        }
    }

    for (int c = 0; c < 4; c++) {
        int kk = c * 32;
        float4 sc4, sh4;
        if (MODE == 1) {
            int c0 = kk + kc;
            float4 smv = *(const float4*)(statsIn + c0);
            float4 sq = *(const float4*)(statsIn + DD + c0);
            float4 gv = *(const float4*)(g + c0);
            float4 bv = *(const float4*)(bt + c0);
            float mu, var, r;
            mu = smv.x * (1.f / NN); var = sq.x * (1.f / NN) - mu * mu;
            r = rsqrtf(var + 1e-5f); sc4.x = gv.x * r; sh4.x = fmaf(-mu, sc4.x, bv.x);
            mu = smv.y * (1.f / NN); var = sq.y * (1.f / NN) - mu * mu;
            r = rsqrtf(var + 1e-5f); sc4.y = gv.y * r; sh4.y = fmaf(-mu, sc4.y, bv.y);
            mu = smv.z * (1.f / NN); var = sq.z * (1.f / NN) - mu * mu;
            r = rsqrtf(var + 1e-5f); sc4.z = gv.z * r; sh4.z = fmaf(-mu, sc4.z, bv.z);
            mu = smv.w * (1.f / NN); var = sq.w * (1.f / NN) - mu * mu;
            r = rsqrtf(var + 1e-5f); sc4.w = gv.w * r; sh4.w = fmaf(-mu, sc4.w, bv.w);
        }

#pragma unroll
        for (int i = 0; i < 4; i++) {
            int row = (t + i * 256) >> 3;
            float4 v = pa[i];
            if (MODE == 1) {
                v.x = fmaxf(fmaf(v.x, sc4.x, sh4.x), 0.f);
                v.y = fmaxf(fmaf(v.y, sc4.y, sh4.y), 0.f);
                v.z = fmaxf(fmaf(v.z, sc4.z, sh4.z), 0.f);
                v.w = fmaxf(fmaf(v.w, sc4.w, sh4.w), 0.f);
            }
            unsigned h01, l01, h23, l23;
            bsplit2(v.x, v.y, h01, l01);
            bsplit2(v.z, v.w, h23, l23);
            unsigned off = (unsigned)(row * 80 + kc * 2);
            *(unsigned*)(sm + off) = h01;
            *(unsigned*)(sm + off + 4) = h23;
            *(unsigned*)(sm + ALO + off) = l01;
            *(unsigned*)(sm + ALO + off + 4) = l23;
        }

        if (c < 3) {
#pragma unroll
            for (int i = 0; i < 4; i++) {
                int row = (t + i * 256) >> 3;
                int gr = row0 + row;
                pa[i] = (gr < NN) ? *(const float4*)(P + (long)gr * DD + kk + 32 + kc)
                                  : make_float4(0.f, 0.f, 0.f, 0.f);
            }
        }

        asm volatile("cp.async.wait_group 0;");
        __syncthreads();

#pragma unroll
        for (int ks = 0; ks < 2; ks++) {
            int kb = ks * 16;
            unsigned ah[2][4], al[2][4];
#pragma unroll
            for (int mi = 0; mi < 2; mi++) {
                unsigned ad = sbase
                    + (unsigned)((m0w + 16 * mi + (lane & 7) + ((lane >> 3) & 1) * 8) * 80
                                 + (kb + (lane >> 4) * 8) * 2);
                ldsm4(ah[mi], ad);
                ldsm4(al[mi], ad + ALO);
            }
#pragma unroll
            for (int q = 0; q < 4; q++) {
                unsigned bd = sbase + WHI
                    + (unsigned)((n0w + 16 * q + ((lane >> 4) & 1) * 8 + (lane & 7)) * 80
                                 + (kb + ((lane >> 3) & 1) * 8) * 2);
                unsigned bh[4], bl[4];
                ldsm4(bh, bd);
                ldsm4(bl, bd + 10240);
#pragma unroll
                for (int mi = 0; mi < 2; mi++) {
#pragma unroll
                    for (int s = 0; s < 2; s++) {
                        int ni = 2 * q + s;
                        mma16816(acc[mi][ni], ah[mi], bh + 2 * s);
                        mma16816(acc[mi][ni], ah[mi], bl + 2 * s);
                        mma16816(acc[mi][ni], al[mi], bh + 2 * s);
                    }
                }
            }
        }
        __syncthreads();

        if (c < 3) {
#pragma unroll
            for (int i = 0; i < 4; i++) {
                int id = t + i * 256;
                int plane = id >> 9, n = (id >> 2) & 127, q = id & 3;
                cpasync16(sbase + WHI + plane * 10240 + n * 80 + q * 16,
                          Wt + plane * 16384 + n * DD + (kk + 32) + q * 8);
            }
            asm volatile("cp.async.commit_group;");
        }
    }

    float* Sa = (float*)sm;            // [4][128]
    float* Sq = (float*)(sm + 2048);   // [4][128]
#pragma unroll
    for (int ni = 0; ni < 8; ni++) {
        int c0 = n0w + 8 * ni + 2 * (lane & 3);
        float s0 = 0.f, q0 = 0.f, s1 = 0.f, q1 = 0.f;
#pragma unroll
        for (int mi = 0; mi < 2; mi++) {
            int r0 = row0 + m0w + 16 * mi + (lane >> 2);
            int r1 = r0 + 8;
            float v0 = acc[mi][ni][0], v1 = acc[mi][ni][1];
            float v2 = acc[mi][ni][2], v3 = acc[mi][ni][3];
            if (r0 < NN) {
                *(float2*)(out + (long)r0 * DD + c0) = make_float2(v0, v1);
                s0 += v0; q0 = fmaf(v0, v0, q0);
                s1 += v1; q1 = fmaf(v1, v1, q1);
            }
            if (r1 < NN) {
                *(float2*)(out + (long)r1 * DD + c0) = make_float2(v2, v3);
                s0 += v2; q0 = fmaf(v2, v2, q0);
                s1 += v3; q1 = fmaf(v3, v3, q1);
            }
        }
#pragma unroll
        for (int m = 4; m <= 16; m <<= 1) {
            s0 += __shfl_xor_sync(0xffffffffu, s0, m);
            q0 += __shfl_xor_sync(0xffffffffu, q0, m);
            s1 += __shfl_xor_sync(0xffffffffu, s1, m);
            q1 += __shfl_xor_sync(0xffffffffu, q1, m);
        }
        if (lane < 4) {
            int cc = n0w + 8 * ni + 2 * lane;
            Sa[wm * 128 + cc] = s0; Sa[wm * 128 + cc + 1] = s1;
            Sq[wm * 128 + cc] = q0; Sq[wm * 128 + cc + 1] = q1;
        }
    }
    __syncthreads();
    if (t < 128) {
        float S = Sa[t] + Sa[128 + t] + Sa[256 + t] + Sa[384 + t];
        float Q = Sq[t] + Sq[128 + t] + Sq[256 + t] + Sq[384 + t];
        atomicAdd(&statsOut[t], S);
        atomicAdd(&statsOut[DD + t], Q);
    }
}

// Final BN+ReLU: write fp16 h; merge readout runs in smem (batch sorted).
__global__ void k_epilogue(const float* __restrict__ Z, const int* __restrict__ batch,
                           const float* __restrict__ g, const float* __restrict__ bt,
                           const float* __restrict__ statsIn, int layer) {
    __shared__ float esc[DD], esh[DD];
    __shared__ float zbuf[8][DD];
    __shared__ int bid[8];
    int t = threadIdx.x;
    int w = t >> 5, lane = t & 31;
    if (t < DD) {
        float mu = statsIn[t] * (1.f / NN);
        float var = statsIn[DD + t] * (1.f / NN) - mu * mu;
        float r = rsqrtf(var + 1e-5f);
        float sc = g[t] * r;
        esc[t] = sc;
        esh[t] = fmaf(-mu, sc, bt[t]);
    }
    __syncthreads();
    int node = blockIdx.x * 8 + w;
    int c4 = lane << 2;
    float4 z = *(const float4*)(Z + (long)node * DD + c4);
    z.x = fmaxf(fmaf(z.x, esc[c4 + 0], esh[c4 + 0]), 0.f);
    z.y = fmaxf(fmaf(z.y, esc[c4 + 1], esh[c4 + 1]), 0.f);
    z.z = fmaxf(fmaf(z.z, esc[c4 + 2], esh[c4 + 2]), 0.f);
    z.w = fmaxf(fmaf(z.w, esc[c4 + 3], esh[c4 + 3]), 0.f);
    *(uint2*)(d_Hb + (long)node * DD + c4) = f4_to_h4(z);
    *(float4*)&zbuf[w][c4] = z;
    if (lane == 0) bid[w] = d_is64 ? batch[2 * node] : batch[node];
    __syncthreads();
    int b = bid[w];
    bool leader = (w == 0) || (bid[w - 1] != b);
    if (leader) {
        float4 s = *(float4*)&zbuf[w][c4];
        for (int u = w + 1; u < 8 && bid[u] == b; u++) {
            float4 q = *(float4*)&zbuf[u][c4];
            s.x += q.x; s.y += q.y; s.z += q.z; s.w += q.w;
        }
        red4(d_readout + b * (NL * DD) + layer * DD + c4, s);
    }
}

__global__ void k_classifier(const float* __restrict__ Wc1, const float* __restrict__ bc1,
                             const float* __restrict__ Wc2, const float* __restrict__ bc2,
                             float* __restrict__ out) {
    int gidx = blockIdx.x;
    int t = threadIdx.x;
    __shared__ float red[NCLS];
    const float* r = d_readout + gidx * (NL * DD);
    float acc = bc1[t];
#pragma unroll 4
    for (int k = 0; k < NL * DD; k++) acc = fmaf(r[k], Wc1[k * DD + t], acc);
    float h = fmaxf(acc, 0.f);
    if (t < NCLS) red[t] = 0.f;
    __syncthreads();
#pragma unroll
    for (int c = 0; c < NCLS; c++) atomicAdd(&red[c], h * Wc2[t * NCLS + c]);
    __syncthreads();
    if (t < NCLS) out[gidx * NCLS + t] = red[t] + bc2[t];
}

// ---------------- launcher ----------------
extern "C" void kernel_launch(void* const* d_in, const int* in_sizes, int n_in,
                              void* d_out, int out_size) {
    const float* x   = (const float*)d_in[0];
    const int*   ei  = (const int*)d_in[1];
    const int*   bat = (const int*)d_in[2];
    const float* W1  = (const float*)d_in[3];
    const float* b1  = (const float*)d_in[4];
    const float* g1  = (const float*)d_in[5];
    const float* bt1 = (const float*)d_in[6];
    const float* W2  = (const float*)d_in[7];
    const float* b2  = (const float*)d_in[8];
    const float* g2  = (const float*)d_in[9];
    const float* bt2 = (const float*)d_in[10];
    const float* Wc1 = (const float*)d_in[11];
    const float* bc1 = (const float*)d_in[12];
    const float* Wc2 = (const float*)d_in[13];
    const float* bc2 = (const float*)d_in[14];
    float* out = (float*)d_out;

    float *pB, *pC, *pStats;
    unsigned short* pWt;
    cudaGetSymbolAddress((void**)&pB, d_B);
    cudaGetSymbolAddress((void**)&pC, d_C);
    cudaGetSymbolAddress((void**)&pStats, d_stats);
    cudaGetSymbolAddress((void**)&pWt, d_Wt);

    // one-time (first call is the uncaptured correctness run)
    static cudaStream_t s2 = nullptr;
    static cudaEvent_t evFork = nullptr, evJoin = nullptr;
    static cudaEvent_t evLayer[NL];            // main -> s2 fork per layer
    static cudaEvent_t evChunk[NL][NCH];       // s2 agg chunk done -> main
    if (!s2) {
        cudaStreamCreateWithFlags(&s2, cudaStreamNonBlocking);
        cudaEventCreateWithFlags(&evFork, cudaEventDisableTiming);
        cudaEventCreateWithFlags(&evJoin, cudaEventDisableTiming);
        for (int l = 0; l < NL; l++) {
            cudaEventCreateWithFlags(&evLayer[l], cudaEventDisableTiming);
            for (int c = 0; c < NCH; c++)
                cudaEventCreateWithFlags(&evChunk[l][c], cudaEventDisableTiming);
        }
    }

    // setup: CSR chain on s2 concurrent with prep on main
    cudaEventRecord(evFork, 0);
    cudaStreamWaitEvent(s2, evFork, 0);
    k_init<<<384, 256, 0, s2>>>(ei);
    k_hist<<<(NE + 255) / 256, 256, 0, s2>>>(ei);
    k_scan1<<<196, 256, 0, s2>>>();
    k_scan23<<<196, 256, 0, s2>>>();
    k_fill<<<(NE + 255) / 256, 256, 0, s2>>>(ei);
    cudaEventRecord(evJoin, s2);

    k_prep<<<6634, 256>>>(x, W1, W2);
    cudaStreamWaitEvent(0, evJoin, 0);   // main now has CSR + Hb + Wt ready

    for (int L = 0; L < NL; L++) {
        float* s1 = pStats + (L * 2 + 0) * (2 * DD);
        float* sB = pStats + (L * 2 + 1) * (2 * DD);

        // fork: agg chunks on s2 (depend on main state: Hb from prep/epilogue)
        cudaEventRecord(evLayer[L], 0);
        cudaStreamWaitEvent(s2, evLayer[L], 0);
        for (int c = 0; c < NCH; c++) {
            int blocks = (CH_NODES[c] / 2 * 32 + 255) / 256;
            k_agg<<<blocks, 256, 0, s2>>>(CH_NODE0[c], CH_NODES[c]);
            cudaEventRecord(evChunk[L][c], s2);
        }

        // main: gemm0 chunk-by-chunk, overlapping later agg chunks
        for (int c = 0; c < NCH; c++) {
            cudaStreamWaitEvent(0, evChunk[L][c], 0);
            k_gemm<0><<<CH_TILES[c], 256>>>(CH_TILE0[c], pB, pWt + L * 32768,
                                            b1 + L * DD, nullptr, nullptr,
                                            nullptr, s1, pC);
        }

        k_gemm<1><<<M_TILES, 256>>>(0, pC, pWt + (3 + L) * 32768, b2 + L * DD,
                                    g1 + L * DD, bt1 + L * DD, s1, sB, pB);
        k_epilogue<<<NN / 8, 256>>>(pB, bat, g2 + L * DD, bt2 + L * DD, sB, L);
    }
    k_classifier<<<NG, 128>>>(Wc1, bc1, Wc2, bc2, out);
}

// round 10
// speedup vs baseline: 1.1571x; 1.1571x over previous
#include <cuda_runtime.h>
#include <cuda_bf16.h>
#include <cuda_fp16.h>

#define NN 50000
#define NE 800000
#define DD 128
#define NL 3
#define NG 256
#define NCLS 10
#define M_TILES 391            // ceil(50000/128)
#define ROWS_PAD (M_TILES*128) // 50048
#define PLSZ ((long)ROWS_PAD * DD)   // ushorts per plane

// ---------------- scratch (static device globals; no allocation) ----------------
__device__ unsigned short d_Hb[NN * DD];       // h as fp16 (gather format)
__device__ unsigned short d_Asp[2 * PLSZ];     // agg pre-split bf16 hi/lo planes (tile layout)
__device__ float d_B[NN * DD];                 // z2
__device__ float d_C[NN * DD];                 // z1
__device__ float d_stats[NL * 2 * 2 * DD];     // per (layer, bn#): [sum | sumsq]
__device__ float d_readout[NG * NL * DD];
__device__ unsigned short d_Wt[6 * 2 * DD * DD];  // [mat][hi/lo][n][k] bf16
__device__ int   d_deg[NN];
__device__ int   d_cur[NN];
__device__ int   d_off[NN + 1];
__device__ int   d_csr[NE];
__device__ int   d_bsum[256];
__device__ int   d_is64;

// ---------------- helpers ----------------
__device__ __forceinline__ void red4(float* p, float4 v) {
    asm volatile("red.global.add.v4.f32 [%0], {%1,%2,%3,%4};"
                 :: "l"(p), "f"(v.x), "f"(v.y), "f"(v.z), "f"(v.w) : "memory");
}
__device__ __forceinline__ unsigned smem_u32(const void* p) {
    unsigned r;
    asm("{ .reg .u64 t; cvta.to.shared.u64 t, %1; cvt.u32.u64 %0, t; }" : "=r"(r) : "l"(p));
    return r;
}
__device__ __forceinline__ void cpasync16(unsigned dst, const void* src) {
    asm volatile("cp.async.cg.shared.global [%0], [%1], 16;" :: "r"(dst), "l"(src));
}
__device__ __forceinline__ void mma16816(float* d, const unsigned* a, const unsigned* b) {
    asm volatile("mma.sync.aligned.m16n8k16.row.col.f32.bf16.bf16.f32 "
                 "{%0,%1,%2,%3},{%4,%5,%6,%7},{%8,%9},{%0,%1,%2,%3};"
                 : "+f"(d[0]), "+f"(d[1]), "+f"(d[2]), "+f"(d[3])
                 : "r"(a[0]), "r"(a[1]), "r"(a[2]), "r"(a[3]), "r"(b[0]), "r"(b[1]));
}
__device__ __forceinline__ void ldsm4(unsigned* r, unsigned addr) {
    asm volatile("ldmatrix.sync.aligned.m8n8.x4.shared.b16 {%0,%1,%2,%3},[%4];"
                 : "=r"(r[0]), "=r"(r[1]), "=r"(r[2]), "=r"(r[3]) : "r"(addr));
}
__device__ __forceinline__ void bsplit2(float x, float y, unsigned& hi, unsigned& lo) {
    __nv_bfloat162 h = __floats2bfloat162_rn(x, y);
    float rx = x - __bfloat162float(h.x);
    float ry = y - __bfloat162float(h.y);
    __nv_bfloat162 l = __floats2bfloat162_rn(rx, ry);
    hi = *(unsigned*)&h;
    lo = *(unsigned*)&l;
}
__device__ __forceinline__ float2 h2f(unsigned u) {
    return __half22float2(*(__half2*)&u);
}
__device__ __forceinline__ uint2 f4_to_h4(float4 v) {
    __half2 a = __floats2half2_rn(v.x, v.y);
    __half2 b = __floats2half2_rn(v.z, v.w);
    uint2 o; o.x = *(unsigned*)&a; o.y = *(unsigned*)&b;
    return o;
}
__device__ __forceinline__ void addrow(float4& a, uint2 v) {
    float2 p0 = h2f(v.x), p1 = h2f(v.y);
    a.x += p0.x; a.y += p0.y; a.z += p1.x; a.w += p1.y;
}

// ---------------- setup kernels ----------------

__global__ void k_init(const int* __restrict__ ei) {
    int i = blockIdx.x * 256 + threadIdx.x;
    if (i == 0) {
        int z = 1;
#pragma unroll
        for (int k = 1; k < 256; k += 2) z &= (ei[k] == 0);
        d_is64 = z;
    }
    if (i < NG * NL * DD) d_readout[i] = 0.f;
    if (i < NL * 2 * 2 * DD) d_stats[i] = 0.f;
    if (i < NN) d_deg[i] = 0;
}

__global__ void k_prep(const float* __restrict__ x,
                       const float* __restrict__ W1, const float* __restrict__ W2) {
    if (blockIdx.x < 6250) {
        int i = blockIdx.x * 256 + threadIdx.x;      // NN*32 = 1.6M
        float4 v = ((const float4*)x)[i];
        ((uint2*)d_Hb)[i] = f4_to_h4(v);
    } else {
        int id = (blockIdx.x - 6250) * 256 + threadIdx.x;  // 6*16384
        int mat = id >> 14;
        int r = id & 16383;
        int n = r & 127, k = r >> 7;
        const float* src = (mat < 3) ? (W1 + mat * 16384) : (W2 + (mat - 3) * 16384);
        float v = src[k * DD + n];
        __nv_bfloat16 hb = __float2bfloat16_rn(v);
        float lof = v - __bfloat162float(hb);
        __nv_bfloat16 lb = __float2bfloat16_rn(lof);
        int base = mat * 32768;
        d_Wt[base + n * DD + k] = __bfloat16_as_ushort(hb);
        d_Wt[base + 16384 + n * DD + k] = __bfloat16_as_ushort(lb);
    }
}

__global__ void k_hist(const int* __restrict__ ei) {
    int e = blockIdx.x * 256 + threadIdx.x;
    if (e >= NE) return;
    int dst = d_is64 ? ei[2 * (NE + e)] : ei[NE + e];
    atomicAdd(&d_deg[dst], 1);
}

__global__ void k_scan1() {
    __shared__ int s[256];
    int t = threadIdx.x;
    int i = blockIdx.x * 256 + t;
    int v = (i < NN) ? d_deg[i] : 0;
    s[t] = v;
    __syncthreads();
#pragma unroll
    for (int d = 1; d < 256; d <<= 1) {
        int x = (t >= d) ? s[t - d] : 0;
        __syncthreads();
        s[t] += x;
        __syncthreads();
    }
    if (i < NN) d_off[i + 1] = s[t];
    if (t == 255) d_bsum[blockIdx.x] = s[255];
}

__global__ void k_scan23() {
    __shared__ int s[256];
    int t = threadIdx.x;
    s[t] = (t < 196) ? d_bsum[t] : 0;
    __syncthreads();
#pragma unroll
    for (int d = 1; d < 256; d <<= 1) {
        int x = (t >= d) ? s[t - d] : 0;
        __syncthreads();
        s[t] += x;
        __syncthreads();
    }
    int b = blockIdx.x;
    int pre = (b == 0) ? 0 : s[b - 1];
    int i = b * 256 + t;
    if (i < NN) { d_off[i + 1] += pre; d_cur[i] = 0; }
    if (i == 0) d_off[0] = 0;
}

__global__ void k_fill(const int* __restrict__ ei) {
    int e = blockIdx.x * 256 + threadIdx.x;
    if (e >= NE) return;
    int src, dst;
    if (d_is64) { src = ei[2 * e]; dst = ei[2 * (NE + e)]; }
    else        { src = ei[e];     dst = ei[NE + e]; }
    int p = atomicAdd(&d_cur[dst], 1);
    d_csr[d_off[dst] + p] = src;
}

// One warp per TWO nodes: full-warp uint2 gather; result written PRE-SPLIT
// (bf16 hi/lo) in gemm0's tile/chunk layout so gemm0 can cp.async it.
__global__ void k_agg() {
    int w = (blockIdx.x * 256 + threadIdx.x) >> 5;
    int n0 = 2 * w, n1 = 2 * w + 1;
    if (n0 >= NN) return;
    int lane = threadIdx.x & 31;
    const uint2* hv = (const uint2*)d_Hb;   // 32 uint2 per node row
    float4 aA, aB;
    { uint2 v = __ldg(&hv[(long)n0 * 32 + lane]); float2 p0 = h2f(v.x), p1 = h2f(v.y);
      aA = make_float4(p0.x, p0.y, p1.x, p1.y); }
    { uint2 v = __ldg(&hv[(long)n1 * 32 + lane]); float2 p0 = h2f(v.x), p1 = h2f(v.y);
      aB = make_float4(p0.x, p0.y, p1.x, p1.y); }
    int j0 = d_off[n0], e0 = d_off[n0 + 1];
    int j1 = e0,        e1 = d_off[n1 + 1];
    while (j0 + 4 <= e0 && j1 + 4 <= e1) {
        int s00 = d_csr[j0], s01 = d_csr[j0 + 1], s02 = d_csr[j0 + 2], s03 = d_csr[j0 + 3];
        int s10 = d_csr[j1], s11 = d_csr[j1 + 1], s12 = d_csr[j1 + 2], s13 = d_csr[j1 + 3];
        uint2 v00 = __ldg(&hv[(long)s00 * 32 + lane]);
        uint2 v01 = __ldg(&hv[(long)s01 * 32 + lane]);
        uint2 v02 = __ldg(&hv[(long)s02 * 32 + lane]);
        uint2 v03 = __ldg(&hv[(long)s03 * 32 + lane]);
        uint2 v10 = __ldg(&hv[(long)s10 * 32 + lane]);
        uint2 v11 = __ldg(&hv[(long)s11 * 32 + lane]);
        uint2 v12 = __ldg(&hv[(long)s12 * 32 + lane]);
        uint2 v13 = __ldg(&hv[(long)s13 * 32 + lane]);
        addrow(aA, v00); addrow(aA, v01); addrow(aA, v02); addrow(aA, v03);
        addrow(aB, v10); addrow(aB, v11); addrow(aB, v12); addrow(aB, v13);
        j0 += 4; j1 += 4;
    }
    for (; j0 + 4 <= e0; j0 += 4) {
        int s0 = d_csr[j0], s1 = d_csr[j0 + 1], s2 = d_csr[j0 + 2], s3 = d_csr[j0 + 3];
        uint2 v0 = __ldg(&hv[(long)s0 * 32 + lane]);
        uint2 v1 = __ldg(&hv[(long)s1 * 32 + lane]);
        uint2 v2 = __ldg(&hv[(long)s2 * 32 + lane]);
        uint2 v3 = __ldg(&hv[(long)s3 * 32 + lane]);
        addrow(aA, v0); addrow(aA, v1); addrow(aA, v2); addrow(aA, v3);
    }
    for (; j0 < e0; j0++) addrow(aA, __ldg(&hv[(long)d_csr[j0] * 32 + lane]));
    for (; j1 + 4 <= e1; j1 += 4) {
        int s0 = d_csr[j1], s1 = d_csr[j1 + 1], s2 = d_csr[j1 + 2], s3 = d_csr[j1 + 3];
        uint2 v0 = __ldg(&hv[(long)s0 * 32 + lane]);
        uint2 v1 = __ldg(&hv[(long)s1 * 32 + lane]);
        uint2 v2 = __ldg(&hv[(long)s2 * 32 + lane]);
        uint2 v3 = __ldg(&hv[(long)s3 * 32 + lane]);
        addrow(aB, v0); addrow(aB, v1); addrow(aB, v2); addrow(aB, v3);
    }
    for (; j1 < e1; j1++) addrow(aB, __ldg(&hv[(long)d_csr[j1] * 32 + lane]));

    // pre-split store: lane owns cols 4*lane..4*lane+3
    // chunk = lane>>3 (k-group of 32), kic = (lane&7)*4 within chunk row (32 ush)
    int tile = n0 >> 7;
    int r0 = n0 & 127;
    int chunk = lane >> 3;
    int kic = (lane & 7) * 4;
    long base = ((long)(tile * 4 + chunk) * 128 + r0) * 32 + kic;
    unsigned h01, l01, h23, l23;
    bsplit2(aA.x, aA.y, h01, l01);
    bsplit2(aA.z, aA.w, h23, l23);
    *(uint2*)(d_Asp + base) = make_uint2(h01, h23);
    *(uint2*)(d_Asp + PLSZ + base) = make_uint2(l01, l23);
    bsplit2(aB.x, aB.y, h01, l01);
    bsplit2(aB.z, aB.w, h23, l23);
    *(uint2*)(d_Asp + base + 32) = make_uint2(h01, h23);
    *(uint2*)(d_Asp + PLSZ + base + 32) = make_uint2(l01, l23);
}

// ---------------- GEMM0: z1 = agg @ W1 + b1 (A via cp.async pre-split planes) ----
// dyn smem 81920: A buf[2] x (hi 10240 + lo 10240), W buf[2] x (hi + lo)
extern __shared__ unsigned char dyn_sm[];
#define G0_SMEM 81920

__global__ void __launch_bounds__(256)
k_gemm0(const unsigned short* __restrict__ Wt, const float* __restrict__ bias,
        float* __restrict__ statsOut, float* __restrict__ out) {
    unsigned char* sm = dyn_sm;
    unsigned sbase = smem_u32(sm);

    int t = threadIdx.x;
    int lane = t & 31, wid = t >> 5;
    int wm = wid & 3, wn = wid >> 2;
    int m0w = wm * 32, n0w = wn * 64;
    int row0 = blockIdx.x * 128;
    long tbase = (long)blockIdx.x * 4 * 128 * 32;   // ushort index of tile chunk0

    // issue chunk 0 (A + W) into buffer 0
    {
#pragma unroll
        for (int i = 0; i < 4; i++) {
            int id = t + i * 256;                   // 0..1023
            int plane = id >> 9;
            int row = (id >> 2) & 127, grp = id & 3;
            cpasync16(sbase + plane * 10240u + (unsigned)(row * 80 + grp * 16),
                      d_Asp + plane * PLSZ + tbase + ((long)row * 32 + grp * 8));
        }
#pragma unroll
        for (int i = 0; i < 4; i++) {
            int id = t + i * 256;
            int plane = id >> 9, n = (id >> 2) & 127, q = id & 3;
            cpasync16(sbase + 40960u + plane * 10240u + (unsigned)(n * 80 + q * 16),
                      Wt + plane * 16384 + n * DD + q * 8);
        }
        asm volatile("cp.async.commit_group;");
    }

    float acc[2][8][4];
#pragma unroll
    for (int ni = 0; ni < 8; ni++) {
        int c0 = n0w + 8 * ni + 2 * (lane & 3);
        float b0 = bias[c0], b1 = bias[c0 + 1];
#pragma unroll
        for (int mi = 0; mi < 2; mi++) {
            acc[mi][ni][0] = b0; acc[mi][ni][1] = b1;
            acc[mi][ni][2] = b0; acc[mi][ni][3] = b1;
        }
    }

    for (int c = 0; c < 4; c++) {
        if (c < 3) {
            int nb = (c + 1) & 1;
            long asrc = tbase + (long)(c + 1) * 128 * 32;
#pragma unroll
            for (int i = 0; i < 4; i++) {
                int id = t + i * 256;
                int plane = id >> 9;
                int row = (id >> 2) & 127, grp = id & 3;
                cpasync16(sbase + nb * 20480u + plane * 10240u + (unsigned)(row * 80 + grp * 16),
                          d_Asp + plane * PLSZ + asrc + ((long)row * 32 + grp * 8));
            }
#pragma unroll
            for (int i = 0; i < 4; i++) {
                int id = t + i * 256;
                int plane = id >> 9, n = (id >> 2) & 127, q = id & 3;
                cpasync16(sbase + 40960u + nb * 20480u + plane * 10240u + (unsigned)(n * 80 + q * 16),
                          Wt + plane * 16384 + n * DD + (c + 1) * 32 + q * 8);
            }
            asm volatile("cp.async.commit_group;");
            asm volatile("cp.async.wait_group 1;");
        } else {
            asm volatile("cp.async.wait_group 0;");
        }
        __syncthreads();

        unsigned abase = sbase + (c & 1) * 20480u;
        unsigned wbase = sbase + 40960u + (c & 1) * 20480u;
#pragma unroll
        for (int ks = 0; ks < 2; ks++) {
            int kb = ks * 16;
            unsigned ah[2][4], al[2][4];
#pragma unroll
            for (int mi = 0; mi < 2; mi++) {
                unsigned ad = abase
                    + (unsigned)((m0w + 16 * mi + (lane & 7) + ((lane >> 3) & 1) * 8) * 80
                                 + (kb + (lane >> 4) * 8) * 2);
                ldsm4(ah[mi], ad);
                ldsm4(al[mi], ad + 10240u);
            }
#pragma unroll
            for (int q = 0; q < 4; q++) {
                unsigned bd = wbase
                    + (unsigned)((n0w + 16 * q + ((lane >> 4) & 1) * 8 + (lane & 7)) * 80
                                 + (kb + ((lane >> 3) & 1) * 8) * 2);
                unsigned bh[4], bl[4];
                ldsm4(bh, bd);
                ldsm4(bl, bd + 10240u);
#pragma unroll
                for (int mi = 0; mi < 2; mi++) {
#pragma unroll
                    for (int s = 0; s < 2; s++) {
                        int ni = 2 * q + s;
                        mma16816(acc[mi][ni], ah[mi], bh + 2 * s);
                        mma16816(acc[mi][ni], ah[mi], bl + 2 * s);
                        mma16816(acc[mi][ni], al[mi], bh + 2 * s);
                    }
                }
            }
        }
        __syncthreads();
    }

    // epilogue: store + fused BN column stats
    float* Sa = (float*)sm;
    float* Sq = (float*)(sm + 2048);
#pragma unroll
    for (int ni = 0; ni < 8; ni++) {
        int c0 = n0w + 8 * ni + 2 * (lane & 3);
        float s0 = 0.f, q0 = 0.f, s1 = 0.f, q1 = 0.f;
#pragma unroll
        for (int mi = 0; mi < 2; mi++) {
            int r0 = row0 + m0w + 16 * mi + (lane >> 2);
            int r1 = r0 + 8;
            float v0 = acc[mi][ni][0], v1 = acc[mi][ni][1];
            float v2 = acc[mi][ni][2], v3 = acc[mi][ni][3];
            if (r0 < NN) {
                *(float2*)(out + (long)r0 * DD + c0) = make_float2(v0, v1);
                s0 += v0; q0 = fmaf(v0, v0, q0);
                s1 += v1; q1 = fmaf(v1, v1, q1);
            }
            if (r1 < NN) {
                *(float2*)(out + (long)r1 * DD + c0) = make_float2(v2, v3);
                s0 += v2; q0 = fmaf(v2, v2, q0);
                s1 += v3; q1 = fmaf(v3, v3, q1);
            }
        }
#pragma unroll
        for (int m = 4; m <= 16; m <<= 1) {
            s0 += __shfl_xor_sync(0xffffffffu, s0, m);
            q0 += __shfl_xor_sync(0xffffffffu, q0, m);
            s1 += __shfl_xor_sync(0xffffffffu, s1, m);
            q1 += __shfl_xor_sync(0xffffffffu, q1, m);
        }
        if (lane < 4) {
            int cc = n0w + 8 * ni + 2 * lane;
            Sa[wm * 128 + cc] = s0; Sa[wm * 128 + cc + 1] = s1;
            Sq[wm * 128 + cc] = q0; Sq[wm * 128 + cc + 1] = q1;
        }
    }
    __syncthreads();
    if (t < 128) {
        float S = Sa[t] + Sa[128 + t] + Sa[256 + t] + Sa[384 + t];
        float Q = Sq[t] + Sq[128 + t] + Sq[256 + t] + Sq[384 + t];
        atomicAdd(&statsOut[t], S);
        atomicAdd(&statsOut[DD + t], Q);
    }
}

// ---------------- GEMM1 (dense fp32 input, BN1 affine + ReLU fused on A load) ----
__global__ void __launch_bounds__(256, 2)
k_gemm1(const float* __restrict__ P, const unsigned short* __restrict__ Wt,
        const float* __restrict__ bias,
        const float* __restrict__ g, const float* __restrict__ bt,
        const float* __restrict__ statsIn, float* __restrict__ statsOut,
        float* __restrict__ out) {
    __shared__ __align__(16) unsigned char sm[40960];
    unsigned sbase = smem_u32(sm);
    const unsigned ALO = 10240, WHI = 20480;

    int t = threadIdx.x;
    int lane = t & 31, wid = t >> 5;
    int wm = wid & 3, wn = wid >> 2;
    int m0w = wm * 32, n0w = wn * 64;
    int row0 = blockIdx.x * 128;
    int kc = (t & 7) << 2;

#pragma unroll
    for (int i = 0; i < 4; i++) {
        int id = t + i * 256;
        int plane = id >> 9, n = (id >> 2) & 127, q = id & 3;
        cpasync16(sbase + WHI + plane * 10240 + n * 80 + q * 16,
                  Wt + plane * 16384 + n * DD + q * 8);
    }
    asm volatile("cp.async.commit_group;");

    float4 pa[4];
#pragma unroll
    for (int i = 0; i < 4; i++) {
        int row = (t + i * 256) >> 3;
        int gr = row0 + row;
        pa[i] = (gr < NN) ? *(const float4*)(P + (long)gr * DD + kc)
                          : make_float4(0.f, 0.f, 0.f, 0.f);
    }

    float acc[2][8][4];
#pragma unroll
    for (int ni = 0; ni < 8; ni++) {
        int c0 = n0w + 8 * ni + 2 * (lane & 3);
        float b0 = bias[c0], b1 = bias[c0 + 1];
#pragma unroll
        for (int mi = 0; mi < 2; mi++) {
            acc[mi][ni][0] = b0; acc[mi][ni][1] = b1;
            acc[mi][ni][2] = b0; acc[mi][ni][3] = b1;
        }
    }

    for (int c = 0; c < 4; c++) {
        int kk = c * 32;
        float4 sc4, sh4;
        {
            int c0 = kk + kc;
            float4 smv = *(const float4*)(statsIn + c0);
            float4 sq = *(const float4*)(statsIn + DD + c0);
            float4 gv = *(const float4*)(g + c0);
            float4 bv = *(const float4*)(bt + c0);
            float mu, var, r;
            mu = smv.x * (1.f / NN); var = sq.x * (1.f / NN) - mu * mu;
            r = rsqrtf(var + 1e-5f); sc4.x = gv.x * r; sh4.x = fmaf(-mu, sc4.x, bv.x);
            mu = smv.y * (1.f / NN); var = sq.y * (1.f / NN) - mu * mu;
            r = rsqrtf(var + 1e-5f); sc4.y = gv.y * r; sh4.y = fmaf(-mu, sc4.y, bv.y);
            mu = smv.z * (1.f / NN); var = sq.z * (1.f / NN) - mu * mu;
            r = rsqrtf(var + 1e-5f); sc4.z = gv.z * r; sh4.z = fmaf(-mu, sc4.z, bv.z);
            mu = smv.w * (1.f / NN); var = sq.w * (1.f / NN) - mu * mu;
            r = rsqrtf(var + 1e-5f); sc4.w = gv.w * r; sh4.w = fmaf(-mu, sc4.w, bv.w);
        }

#pragma unroll
        for (int i = 0; i < 4; i++) {
            int row = (t + i * 256) >> 3;
            float4 v = pa[i];
            v.x = fmaxf(fmaf(v.x, sc4.x, sh4.x), 0.f);
            v.y = fmaxf(fmaf(v.y, sc4.y, sh4.y), 0.f);
            v.z = fmaxf(fmaf(v.z, sc4.z, sh4.z), 0.f);
            v.w = fmaxf(fmaf(v.w, sc4.w, sh4.w), 0.f);
            unsigned h01, l01, h23, l23;
            bsplit2(v.x, v.y, h01, l01);
            bsplit2(v.z, v.w, h23, l23);
            unsigned off = (unsigned)(row * 80 + kc * 2);
            *(unsigned*)(sm + off) = h01;
            *(unsigned*)(sm + off + 4) = h23;
            *(unsigned*)(sm + ALO + off) = l01;
            *(unsigned*)(sm + ALO + off + 4) = l23;
        }

        if (c < 3) {
#pragma unroll
            for (int i = 0; i < 4; i++) {
                int row = (t + i * 256) >> 3;
                int gr = row0 + row;
                pa[i] = (gr < NN) ? *(const float4*)(P + (long)gr * DD + kk + 32 + kc)
                                  : make_float4(0.f, 0.f, 0.f, 0.f);
            }
        }

        asm volatile("cp.async.wait_group 0;");
        __syncthreads();

#pragma unroll
        for (int ks = 0; ks < 2; ks++) {
            int kb = ks * 16;
            unsigned ah[2][4], al[2][4];
#pragma unroll
            for (int mi = 0; mi < 2; mi++) {
                unsigned ad = sbase
                    + (unsigned)((m0w + 16 * mi + (lane & 7) + ((lane >> 3) & 1) * 8) * 80
                                 + (kb + (lane >> 4) * 8) * 2);
                ldsm4(ah[mi], ad);
                ldsm4(al[mi], ad + ALO);
            }
#pragma unroll
            for (int q = 0; q < 4; q++) {
                unsigned bd = sbase + WHI
                    + (unsigned)((n0w + 16 * q + ((lane >> 4) & 1) * 8 + (lane & 7)) * 80
                                 + (kb + ((lane >> 3) & 1) * 8) * 2);
                unsigned bh[4], bl[4];
                ldsm4(bh, bd);
                ldsm4(bl, bd + 10240);
#pragma unroll
                for (int mi = 0; mi < 2; mi++) {
#pragma unroll
                    for (int s = 0; s < 2; s++) {
                        int ni = 2 * q + s;
                        mma16816(acc[mi][ni], ah[mi], bh + 2 * s);
                        mma16816(acc[mi][ni], ah[mi], bl + 2 * s);
                        mma16816(acc[mi][ni], al[mi], bh + 2 * s);
                    }
                }
            }
        }
        __syncthreads();

        if (c < 3) {
#pragma unroll
            for (int i = 0; i < 4; i++) {
                int id = t + i * 256;
                int plane = id >> 9, n = (id >> 2) & 127, q = id & 3;
                cpasync16(sbase + WHI + plane * 10240 + n * 80 + q * 16,
                          Wt + plane * 16384 + n * DD + (kk + 32) + q * 8);
            }
            asm volatile("cp.async.commit_group;");
        }
    }

    float* Sa = (float*)sm;
    float* Sq = (float*)(sm + 2048);
#pragma unroll
    for (int ni = 0; ni < 8; ni++) {
        int c0 = n0w + 8 * ni + 2 * (lane & 3);
        float s0 = 0.f, q0 = 0.f, s1 = 0.f, q1 = 0.f;
#pragma unroll
        for (int mi = 0; mi < 2; mi++) {
            int r0 = row0 + m0w + 16 * mi + (lane >> 2);
            int r1 = r0 + 8;
            float v0 = acc[mi][ni][0], v1 = acc[mi][ni][1];
            float v2 = acc[mi][ni][2], v3 = acc[mi][ni][3];
            if (r0 < NN) {
                *(float2*)(out + (long)r0 * DD + c0) = make_float2(v0, v1);
                s0 += v0; q0 = fmaf(v0, v0, q0);
                s1 += v1; q1 = fmaf(v1, v1, q1);
            }
            if (r1 < NN) {
                *(float2*)(out + (long)r1 * DD + c0) = make_float2(v2, v3);
                s0 += v2; q0 = fmaf(v2, v2, q0);
                s1 += v3; q1 = fmaf(v3, v3, q1);
            }
        }
#pragma unroll
        for (int m = 4; m <= 16; m <<= 1) {
            s0 += __shfl_xor_sync(0xffffffffu, s0, m);
            q0 += __shfl_xor_sync(0xffffffffu, q0, m);
            s1 += __shfl_xor_sync(0xffffffffu, s1, m);
            q1 += __shfl_xor_sync(0xffffffffu, q1, m);
        }
        if (lane < 4) {
            int cc = n0w + 8 * ni + 2 * lane;
            Sa[wm * 128 + cc] = s0; Sa[wm * 128 + cc + 1] = s1;
            Sq[wm * 128 + cc] = q0; Sq[wm * 128 + cc + 1] = q1;
        }
    }
    __syncthreads();
    if (t < 128) {
        float S = Sa[t] + Sa[128 + t] + Sa[256 + t] + Sa[384 + t];
        float Q = Sq[t] + Sq[128 + t] + Sq[256 + t] + Sq[384 + t];
        atomicAdd(&statsOut[t], S);
        atomicAdd(&statsOut[DD + t], Q);
    }
}

// Final BN+ReLU: write fp16 h; merge readout runs in smem (batch sorted).
__global__ void k_epilogue(const float* __restrict__ Z, const int* __restrict__ batch,
                           const float* __restrict__ g, const float* __restrict__ bt,
                           const float* __restrict__ statsIn, int layer) {
    __shared__ float esc[DD], esh[DD];
    __shared__ float zbuf[8][DD];
    __shared__ int bid[8];
    int t = threadIdx.x;
    int w = t >> 5, lane = t & 31;
    if (t < DD) {
        float mu = statsIn[t] * (1.f / NN);
        float var = statsIn[DD + t] * (1.f / NN) - mu * mu;
        float r = rsqrtf(var + 1e-5f);
        float sc = g[t] * r;
        esc[t] = sc;
        esh[t] = fmaf(-mu, sc, bt[t]);
    }
    __syncthreads();
    int node = blockIdx.x * 8 + w;
    int c4 = lane << 2;
    float4 z = *(const float4*)(Z + (long)node * DD + c4);
    z.x = fmaxf(fmaf(z.x, esc[c4 + 0], esh[c4 + 0]), 0.f);
    z.y = fmaxf(fmaf(z.y, esc[c4 + 1], esh[c4 + 1]), 0.f);
    z.z = fmaxf(fmaf(z.z, esc[c4 + 2], esh[c4 + 2]), 0.f);
    z.w = fmaxf(fmaf(z.w, esc[c4 + 3], esh[c4 + 3]), 0.f);
    *(uint2*)(d_Hb + (long)node * DD + c4) = f4_to_h4(z);
    *(float4*)&zbuf[w][c4] = z;
    if (lane == 0) bid[w] = d_is64 ? batch[2 * node] : batch[node];
    __syncthreads();
    int b = bid[w];
    bool leader = (w == 0) || (bid[w - 1] != b);
    if (leader) {
        float4 s = *(float4*)&zbuf[w][c4];
        for (int u = w + 1; u < 8 && bid[u] == b; u++) {
            float4 q = *(float4*)&zbuf[u][c4];
            s.x += q.x; s.y += q.y; s.z += q.z; s.w += q.w;
        }
        red4(d_readout + b * (NL * DD) + layer * DD + c4, s);
    }
}

__global__ void k_classifier(const float* __restrict__ Wc1, const float* __restrict__ bc1,
                             const float* __restrict__ Wc2, const float* __restrict__ bc2,
                             float* __restrict__ out) {
    int gidx = blockIdx.x;
    int t = threadIdx.x;
    __shared__ float red[NCLS];
    const float* r = d_readout + gidx * (NL * DD);
    float acc = bc1[t];
#pragma unroll 4
    for (int k = 0; k < NL * DD; k++) acc = fmaf(r[k], Wc1[k * DD + t], acc);
    float h = fmaxf(acc, 0.f);
    if (t < NCLS) red[t] = 0.f;
    __syncthreads();
#pragma unroll
    for (int c = 0; c < NCLS; c++) atomicAdd(&red[c], h * Wc2[t * NCLS + c]);
    __syncthreads();
    if (t < NCLS) out[gidx * NCLS + t] = red[t] + bc2[t];
}

// ---------------- launcher ----------------
extern "C" void kernel_launch(void* const* d_in, const int* in_sizes, int n_in,
                              void* d_out, int out_size) {
    const float* x   = (const float*)d_in[0];
    const int*   ei  = (const int*)d_in[1];
    const int*   bat = (const int*)d_in[2];
    const float* W1  = (const float*)d_in[3];
    const float* b1  = (const float*)d_in[4];
    const float* g1  = (const float*)d_in[5];
    const float* bt1 = (const float*)d_in[6];
    const float* W2  = (const float*)d_in[7];
    const float* b2  = (const float*)d_in[8];
    const float* g2  = (const float*)d_in[9];
    const float* bt2 = (const float*)d_in[10];
    const float* Wc1 = (const float*)d_in[11];
    const float* bc1 = (const float*)d_in[12];
    const float* Wc2 = (const float*)d_in[13];
    const float* bc2 = (const float*)d_in[14];
    float* out = (float*)d_out;

    float *pB, *pC, *pStats;
    unsigned short* pWt;
    cudaGetSymbolAddress((void**)&pB, d_B);
    cudaGetSymbolAddress((void**)&pC, d_C);
    cudaGetSymbolAddress((void**)&pStats, d_stats);
    cudaGetSymbolAddress((void**)&pWt, d_Wt);

    // one-time (first call is the uncaptured correctness run)
    static cudaStream_t sCSR = nullptr;
    static cudaEvent_t evFork = nullptr, evJoin = nullptr;
    if (!sCSR) {
        cudaStreamCreateWithFlags(&sCSR, cudaStreamNonBlocking);
        cudaEventCreateWithFlags(&evFork, cudaEventDisableTiming);
        cudaEventCreateWithFlags(&evJoin, cudaEventDisableTiming);
        cudaFuncSetAttribute(k_gemm0, cudaFuncAttributeMaxDynamicSharedMemorySize, G0_SMEM);
    }

    // setup: CSR chain on sCSR concurrent with prep on main
    cudaEventRecord(evFork, 0);
    cudaStreamWaitEvent(sCSR, evFork, 0);
    k_init<<<384, 256, 0, sCSR>>>(ei);
    k_hist<<<(NE + 255) / 256, 256, 0, sCSR>>>(ei);
    k_scan1<<<196, 256, 0, sCSR>>>();
    k_scan23<<<196, 256, 0, sCSR>>>();
    k_fill<<<(NE + 255) / 256, 256, 0, sCSR>>>(ei);
    cudaEventRecord(evJoin, sCSR);

    k_prep<<<6634, 256>>>(x, W1, W2);
    cudaStreamWaitEvent(0, evJoin, 0);   // join before the layer loop

    for (int L = 0; L < NL; L++) {
        float* s1 = pStats + (L * 2 + 0) * (2 * DD);
        float* s2 = pStats + (L * 2 + 1) * (2 * DD);
        k_agg<<<3125, 256>>>();
        k_gemm0<<<M_TILES, 256, G0_SMEM>>>(pWt + L * 32768, b1 + L * DD, s1, pC);
        k_gemm1<<<M_TILES, 256>>>(pC, pWt + (3 + L) * 32768, b2 + L * DD,
                                  g1 + L * DD, bt1 + L * DD, s1, s2, pB);
        k_epilogue<<<NN / 8, 256>>>(pB, bat, g2 + L * DD, bt2 + L * DD, s2, L);
    }
    k_classifier<<<NG, 128>>>(Wc1, bc1, Wc2, bc2, out);
}

// round 11
// speedup vs baseline: 1.2346x; 1.0671x over previous
#include <cuda_runtime.h>
#include <cuda_bf16.h>
#include <cuda_fp16.h>

#define NN 50000
#define NE 800000
#define DD 128
#define NL 3
#define NG 256
#define NCLS 10
#define M_TILES 391   // ceil(50000/128)

// ---------------- scratch (static device globals; no allocation) ----------------
__device__ unsigned short d_Hb[NN * DD];     // h as fp16 (gather format)
__device__ float d_B[NN * DD];               // agg (fp32); z2 stored as fp16 in low half
__device__ float d_C[NN * DD];               // z1
__device__ float d_stats[NL * 2 * 2 * DD];   // per (layer, bn#): [sum | sumsq]
__device__ float d_readout[NG * NL * DD];
__device__ unsigned short d_Wt[6 * 2 * DD * DD];  // [mat][hi/lo][n][k] bf16
__device__ int   d_deg[NN];
__device__ int   d_cur[NN];
__device__ int   d_off[NN + 1];
__device__ int   d_csr[NE];
__device__ int   d_bsum[256];
__device__ int   d_is64;

// ---------------- helpers ----------------
__device__ __forceinline__ void red4(float* p, float4 v) {
    asm volatile("red.global.add.v4.f32 [%0], {%1,%2,%3,%4};"
                 :: "l"(p), "f"(v.x), "f"(v.y), "f"(v.z), "f"(v.w) : "memory");
}
__device__ __forceinline__ unsigned smem_u32(const void* p) {
    unsigned r;
    asm("{ .reg .u64 t; cvta.to.shared.u64 t, %1; cvt.u32.u64 %0, t; }" : "=r"(r) : "l"(p));
    return r;
}
__device__ __forceinline__ void cpasync16(unsigned dst, const void* src) {
    asm volatile("cp.async.cg.shared.global [%0], [%1], 16;" :: "r"(dst), "l"(src));
}
__device__ __forceinline__ void mma16816(float* d, const unsigned* a, const unsigned* b) {
    asm volatile("mma.sync.aligned.m16n8k16.row.col.f32.bf16.bf16.f32 "
                 "{%0,%1,%2,%3},{%4,%5,%6,%7},{%8,%9},{%0,%1,%2,%3};"
                 : "+f"(d[0]), "+f"(d[1]), "+f"(d[2]), "+f"(d[3])
                 : "r"(a[0]), "r"(a[1]), "r"(a[2]), "r"(a[3]), "r"(b[0]), "r"(b[1]));
}
__device__ __forceinline__ void ldsm4(unsigned* r, unsigned addr) {
    asm volatile("ldmatrix.sync.aligned.m8n8.x4.shared.b16 {%0,%1,%2,%3},[%4];"
                 : "=r"(r[0]), "=r"(r[1]), "=r"(r[2]), "=r"(r[3]) : "r"(addr));
}
__device__ __forceinline__ void bsplit2(float x, float y, unsigned& hi, unsigned& lo) {
    __nv_bfloat162 h = __floats2bfloat162_rn(x, y);
    float rx = x - __bfloat162float(h.x);
    float ry = y - __bfloat162float(h.y);
    __nv_bfloat162 l = __floats2bfloat162_rn(rx, ry);
    hi = *(unsigned*)&h;
    lo = *(unsigned*)&l;
}
__device__ __forceinline__ float2 h2f(unsigned u) {
    return __half22float2(*(__half2*)&u);
}
__device__ __forceinline__ unsigned f2_to_h2(float x, float y) {
    __half2 a = __floats2half2_rn(x, y);
    return *(unsigned*)&a;
}
__device__ __forceinline__ uint2 f4_to_h4(float4 v) {
    uint2 o; o.x = f2_to_h2(v.x, v.y); o.y = f2_to_h2(v.z, v.w);
    return o;
}
__device__ __forceinline__ void addrow(float4& a, uint2 v) {
    float2 p0 = h2f(v.x), p1 = h2f(v.y);
    a.x += p0.x; a.y += p0.y; a.z += p1.x; a.w += p1.y;
}

// ---------------- setup kernels ----------------

__global__ void k_init(const int* __restrict__ ei) {
    int i = blockIdx.x * 256 + threadIdx.x;
    if (i == 0) {
        int z = 1;
#pragma unroll
        for (int k = 1; k < 256; k += 2) z &= (ei[k] == 0);
        d_is64 = z;
    }
    if (i < NG * NL * DD) d_readout[i] = 0.f;
    if (i < NL * 2 * 2 * DD) d_stats[i] = 0.f;
    if (i < NN) d_deg[i] = 0;
}

__global__ void k_prep(const float* __restrict__ x,
                       const float* __restrict__ W1, const float* __restrict__ W2) {
    if (blockIdx.x < 6250) {
        int i = blockIdx.x * 256 + threadIdx.x;      // NN*32 = 1.6M
        float4 v = ((const float4*)x)[i];
        ((uint2*)d_Hb)[i] = f4_to_h4(v);
    } else {
        int id = (blockIdx.x - 6250) * 256 + threadIdx.x;  // 6*16384
        int mat = id >> 14;
        int r = id & 16383;
        int n = r & 127, k = r >> 7;
        const float* src = (mat < 3) ? (W1 + mat * 16384) : (W2 + (mat - 3) * 16384);
        float v = src[k * DD + n];
        __nv_bfloat16 hb = __float2bfloat16_rn(v);
        float lof = v - __bfloat162float(hb);
        __nv_bfloat16 lb = __float2bfloat16_rn(lof);
        int base = mat * 32768;
        d_Wt[base + n * DD + k] = __bfloat16_as_ushort(hb);
        d_Wt[base + 16384 + n * DD + k] = __bfloat16_as_ushort(lb);
    }
}

__global__ void k_hist(const int* __restrict__ ei) {
    int e = blockIdx.x * 256 + threadIdx.x;
    if (e >= NE) return;
    int dst = d_is64 ? ei[2 * (NE + e)] : ei[NE + e];
    atomicAdd(&d_deg[dst], 1);
}

__global__ void k_scan1() {
    __shared__ int s[256];
    int t = threadIdx.x;
    int i = blockIdx.x * 256 + t;
    int v = (i < NN) ? d_deg[i] : 0;
    s[t] = v;
    __syncthreads();
#pragma unroll
    for (int d = 1; d < 256; d <<= 1) {
        int x = (t >= d) ? s[t - d] : 0;
        __syncthreads();
        s[t] += x;
        __syncthreads();
    }
    if (i < NN) d_off[i + 1] = s[t];
    if (t == 255) d_bsum[blockIdx.x] = s[255];
}

__global__ void k_scan23() {
    __shared__ int s[256];
    int t = threadIdx.x;
    s[t] = (t < 196) ? d_bsum[t] : 0;
    __syncthreads();
#pragma unroll
    for (int d = 1; d < 256; d <<= 1) {
        int x = (t >= d) ? s[t - d] : 0;
        __syncthreads();
        s[t] += x;
        __syncthreads();
    }
    int b = blockIdx.x;
    int pre = (b == 0) ? 0 : s[b - 1];
    int i = b * 256 + t;
    if (i < NN) { d_off[i + 1] += pre; d_cur[i] = 0; }
    if (i == 0) d_off[0] = 0;
}

__global__ void k_fill(const int* __restrict__ ei) {
    int e = blockIdx.x * 256 + threadIdx.x;
    if (e >= NE) return;
    int src, dst;
    if (d_is64) { src = ei[2 * e]; dst = ei[2 * (NE + e)]; }
    else        { src = ei[e];     dst = ei[NE + e]; }
    int p = atomicAdd(&d_cur[dst], 1);
    d_csr[d_off[dst] + p] = src;
}

// One warp per TWO nodes: full-warp uint2 gather (256B row), joint 4+4 loop.
__global__ void k_agg() {
    int w = (blockIdx.x * 256 + threadIdx.x) >> 5;
    int n0 = 2 * w, n1 = 2 * w + 1;
    if (n0 >= NN) return;
    int lane = threadIdx.x & 31;
    const uint2* hv = (const uint2*)d_Hb;   // 32 uint2 per node row
    float4 aA, aB;
    { uint2 v = __ldg(&hv[(long)n0 * 32 + lane]); float2 p0 = h2f(v.x), p1 = h2f(v.y);
      aA = make_float4(p0.x, p0.y, p1.x, p1.y); }
    { uint2 v = __ldg(&hv[(long)n1 * 32 + lane]); float2 p0 = h2f(v.x), p1 = h2f(v.y);
      aB = make_float4(p0.x, p0.y, p1.x, p1.y); }
    int j0 = d_off[n0], e0 = d_off[n0 + 1];
    int j1 = e0,        e1 = d_off[n1 + 1];
    while (j0 + 4 <= e0 && j1 + 4 <= e1) {
        int s00 = d_csr[j0], s01 = d_csr[j0 + 1], s02 = d_csr[j0 + 2], s03 = d_csr[j0 + 3];
        int s10 = d_csr[j1], s11 = d_csr[j1 + 1], s12 = d_csr[j1 + 2], s13 = d_csr[j1 + 3];
        uint2 v00 = __ldg(&hv[(long)s00 * 32 + lane]);
        uint2 v01 = __ldg(&hv[(long)s01 * 32 + lane]);
        uint2 v02 = __ldg(&hv[(long)s02 * 32 + lane]);
        uint2 v03 = __ldg(&hv[(long)s03 * 32 + lane]);
        uint2 v10 = __ldg(&hv[(long)s10 * 32 + lane]);
        uint2 v11 = __ldg(&hv[(long)s11 * 32 + lane]);
        uint2 v12 = __ldg(&hv[(long)s12 * 32 + lane]);
        uint2 v13 = __ldg(&hv[(long)s13 * 32 + lane]);
        addrow(aA, v00); addrow(aA, v01); addrow(aA, v02); addrow(aA, v03);
        addrow(aB, v10); addrow(aB, v11); addrow(aB, v12); addrow(aB, v13);
        j0 += 4; j1 += 4;
    }
    for (; j0 + 4 <= e0; j0 += 4) {
        int s0 = d_csr[j0], s1 = d_csr[j0 + 1], s2 = d_csr[j0 + 2], s3 = d_csr[j0 + 3];
        uint2 v0 = __ldg(&hv[(long)s0 * 32 + lane]);
        uint2 v1 = __ldg(&hv[(long)s1 * 32 + lane]);
        uint2 v2 = __ldg(&hv[(long)s2 * 32 + lane]);
        uint2 v3 = __ldg(&hv[(long)s3 * 32 + lane]);
        addrow(aA, v0); addrow(aA, v1); addrow(aA, v2); addrow(aA, v3);
    }
    for (; j0 < e0; j0++) addrow(aA, __ldg(&hv[(long)d_csr[j0] * 32 + lane]));
    for (; j1 + 4 <= e1; j1 += 4) {
        int s0 = d_csr[j1], s1 = d_csr[j1 + 1], s2 = d_csr[j1 + 2], s3 = d_csr[j1 + 3];
        uint2 v0 = __ldg(&hv[(long)s0 * 32 + lane]);
        uint2 v1 = __ldg(&hv[(long)s1 * 32 + lane]);
        uint2 v2 = __ldg(&hv[(long)s2 * 32 + lane]);
        uint2 v3 = __ldg(&hv[(long)s3 * 32 + lane]);
        addrow(aB, v0); addrow(aB, v1); addrow(aB, v2); addrow(aB, v3);
    }
    for (; j1 < e1; j1++) addrow(aB, __ldg(&hv[(long)d_csr[j1] * 32 + lane]));
    ((float4*)d_B)[(long)n0 * 32 + lane] = aA;
    ((float4*)d_B)[(long)n1 * 32 + lane] = aB;
}

// ---------------- tensor-core GEMM (bf16-split, fp32-accurate) ----------------
// MODE 0: f = identity, fp32 output (z1)
// MODE 1: f = relu(P*scale+shift) from statsIn, fp16 output (z2)
template <int MODE>
__global__ void __launch_bounds__(256, 2)
k_gemm(const float* __restrict__ P, const unsigned short* __restrict__ Wt,
       const float* __restrict__ bias,
       const float* __restrict__ g, const float* __restrict__ bt,
       const float* __restrict__ statsIn, float* __restrict__ statsOut,
       float* __restrict__ out) {
    __shared__ __align__(16) unsigned char sm[40960];
    unsigned sbase = smem_u32(sm);
    const unsigned ALO = 10240, WHI = 20480;

    int t = threadIdx.x;
    int lane = t & 31, wid = t >> 5;
    int wm = wid & 3, wn = wid >> 2;
    int m0w = wm * 32, n0w = wn * 64;
    int row0 = blockIdx.x * 128;
    int kc = (t & 7) << 2;

#pragma unroll
    for (int i = 0; i < 4; i++) {
        int id = t + i * 256;
        int plane = id >> 9, n = (id >> 2) & 127, q = id & 3;
        cpasync16(sbase + WHI + plane * 10240 + n * 80 + q * 16,
                  Wt + plane * 16384 + n * DD + q * 8);
    }
    asm volatile("cp.async.commit_group;");

    float4 pa[4];
#pragma unroll
    for (int i = 0; i < 4; i++) {
        int row = (t + i * 256) >> 3;
        int gr = row0 + row;
        pa[i] = (gr < NN) ? *(const float4*)(P + (long)gr * DD + kc)
                          : make_float4(0.f, 0.f, 0.f, 0.f);
    }

    float acc[2][8][4];
#pragma unroll
    for (int ni = 0; ni < 8; ni++) {
        int c0 = n0w + 8 * ni + 2 * (lane & 3);
        float b0 = bias[c0], b1 = bias[c0 + 1];
#pragma unroll
        for (int mi = 0; mi < 2; mi++) {
            acc[mi][ni][0] = b0; acc[mi][ni][1] = b1;
            acc[mi][ni][2] = b0; acc[mi][ni][3] = b1;
        }
    }

    for (int c = 0; c < 4; c++) {
        int kk = c * 32;
        float4 sc4, sh4;
        if (MODE == 1) {
            int c0 = kk + kc;
            float4 smv = *(const float4*)(statsIn + c0);
            float4 sq = *(const float4*)(statsIn + DD + c0);
            float4 gv = *(const float4*)(g + c0);
            float4 bv = *(const float4*)(bt + c0);
            float mu, var, r;
            mu = smv.x * (1.f / NN); var = sq.x * (1.f / NN) - mu * mu;
            r = rsqrtf(var + 1e-5f); sc4.x = gv.x * r; sh4.x = fmaf(-mu, sc4.x, bv.x);
            mu = smv.y * (1.f / NN); var = sq.y * (1.f / NN) - mu * mu;
            r = rsqrtf(var + 1e-5f); sc4.y = gv.y * r; sh4.y = fmaf(-mu, sc4.y, bv.y);
            mu = smv.z * (1.f / NN); var = sq.z * (1.f / NN) - mu * mu;
            r = rsqrtf(var + 1e-5f); sc4.z = gv.z * r; sh4.z = fmaf(-mu, sc4.z, bv.z);
            mu = smv.w * (1.f / NN); var = sq.w * (1.f / NN) - mu * mu;
            r = rsqrtf(var + 1e-5f); sc4.w = gv.w * r; sh4.w = fmaf(-mu, sc4.w, bv.w);
        }

#pragma unroll
        for (int i = 0; i < 4; i++) {
            int row = (t + i * 256) >> 3;
            float4 v = pa[i];
            if (MODE == 1) {
                v.x = fmaxf(fmaf(v.x, sc4.x, sh4.x), 0.f);
                v.y = fmaxf(fmaf(v.y, sc4.y, sh4.y), 0.f);
                v.z = fmaxf(fmaf(v.z, sc4.z, sh4.z), 0.f);
                v.w = fmaxf(fmaf(v.w, sc4.w, sh4.w), 0.f);
            }
            unsigned h01, l01, h23, l23;
            bsplit2(v.x, v.y, h01, l01);
            bsplit2(v.z, v.w, h23, l23);
            unsigned off = (unsigned)(row * 80 + kc * 2);
            *(unsigned*)(sm + off) = h01;
            *(unsigned*)(sm + off + 4) = h23;
            *(unsigned*)(sm + ALO + off) = l01;
            *(unsigned*)(sm + ALO + off + 4) = l23;
        }

        if (c < 3) {
#pragma unroll
            for (int i = 0; i < 4; i++) {
                int row = (t + i * 256) >> 3;
                int gr = row0 + row;
                pa[i] = (gr < NN) ? *(const float4*)(P + (long)gr * DD + kk + 32 + kc)
                                  : make_float4(0.f, 0.f, 0.f, 0.f);
            }
        }

        asm volatile("cp.async.wait_group 0;");
        __syncthreads();

#pragma unroll
        for (int ks = 0; ks < 2; ks++) {
            int kb = ks * 16;
            unsigned ah[2][4], al[2][4];
#pragma unroll
            for (int mi = 0; mi < 2; mi++) {
                unsigned ad = sbase
                    + (unsigned)((m0w + 16 * mi + (lane & 7) + ((lane >> 3) & 1) * 8) * 80
                                 + (kb + (lane >> 4) * 8) * 2);
                ldsm4(ah[mi], ad);
                ldsm4(al[mi], ad + ALO);
            }
#pragma unroll
            for (int q = 0; q < 4; q++) {
                unsigned bd = sbase + WHI
                    + (unsigned)((n0w + 16 * q + ((lane >> 4) & 1) * 8 + (lane & 7)) * 80
                                 + (kb + ((lane >> 3) & 1) * 8) * 2);
                unsigned bh[4], bl[4];
                ldsm4(bh, bd);
                ldsm4(bl, bd + 10240);
#pragma unroll
                for (int mi = 0; mi < 2; mi++) {
#pragma unroll
                    for (int s = 0; s < 2; s++) {
                        int ni = 2 * q + s;
                        mma16816(acc[mi][ni], ah[mi], bh + 2 * s);
                        mma16816(acc[mi][ni], ah[mi], bl + 2 * s);
                        mma16816(acc[mi][ni], al[mi], bh + 2 * s);
                    }
                }
            }
        }
        __syncthreads();

        if (c < 3) {
#pragma unroll
            for (int i = 0; i < 4; i++) {
                int id = t + i * 256;
                int plane = id >> 9, n = (id >> 2) & 127, q = id & 3;
                cpasync16(sbase + WHI + plane * 10240 + n * 80 + q * 16,
                          Wt + plane * 16384 + n * DD + (kk + 32) + q * 8);
            }
            asm volatile("cp.async.commit_group;");
        }
    }

    float* Sa = (float*)sm;            // [4][128]
    float* Sq = (float*)(sm + 2048);   // [4][128]
    unsigned short* outh = (unsigned short*)out;
#pragma unroll
    for (int ni = 0; ni < 8; ni++) {
        int c0 = n0w + 8 * ni + 2 * (lane & 3);
        float s0 = 0.f, q0 = 0.f, s1 = 0.f, q1 = 0.f;
#pragma unroll
        for (int mi = 0; mi < 2; mi++) {
            int r0 = row0 + m0w + 16 * mi + (lane >> 2);
            int r1 = r0 + 8;
            float v0 = acc[mi][ni][0], v1 = acc[mi][ni][1];
            float v2 = acc[mi][ni][2], v3 = acc[mi][ni][3];
            if (r0 < NN) {
                if (MODE == 1)
                    *(unsigned*)(outh + (long)r0 * DD + c0) = f2_to_h2(v0, v1);
                else
                    *(float2*)(out + (long)r0 * DD + c0) = make_float2(v0, v1);
                s0 += v0; q0 = fmaf(v0, v0, q0);
                s1 += v1; q1 = fmaf(v1, v1, q1);
            }
            if (r1 < NN) {
                if (MODE == 1)
                    *(unsigned*)(outh + (long)r1 * DD + c0) = f2_to_h2(v2, v3);
                else
                    *(float2*)(out + (long)r1 * DD + c0) = make_float2(v2, v3);
                s0 += v2; q0 = fmaf(v2, v2, q0);
                s1 += v3; q1 = fmaf(v3, v3, q1);
            }
        }
#pragma unroll
        for (int m = 4; m <= 16; m <<= 1) {
            s0 += __shfl_xor_sync(0xffffffffu, s0, m);
            q0 += __shfl_xor_sync(0xffffffffu, q0, m);
            s1 += __shfl_xor_sync(0xffffffffu, s1, m);
            q1 += __shfl_xor_sync(0xffffffffu, q1, m);
        }
        if (lane < 4) {
            int cc = n0w + 8 * ni + 2 * lane;
            Sa[wm * 128 + cc] = s0; Sa[wm * 128 + cc + 1] = s1;
            Sq[wm * 128 + cc] = q0; Sq[wm * 128 + cc + 1] = q1;
        }
    }
    __syncthreads();
    if (t < 128) {
        float S = Sa[t] + Sa[128 + t] + Sa[256 + t] + Sa[384 + t];
        float Q = Sq[t] + Sq[128 + t] + Sq[256 + t] + Sq[384 + t];
        atomicAdd(&statsOut[t], S);
        atomicAdd(&statsOut[DD + t], Q);
    }
}

// Final BN+ReLU: read fp16 z2, write fp16 h; merge readout runs (batch sorted).
__global__ void k_epilogue(const unsigned short* __restrict__ Z, const int* __restrict__ batch,
                           const float* __restrict__ g, const float* __restrict__ bt,
                           const float* __restrict__ statsIn, int layer) {
    __shared__ float esc[DD], esh[DD];
    __shared__ float zbuf[8][DD];
    __shared__ int bid[8];
    int t = threadIdx.x;
    int w = t >> 5, lane = t & 31;
    if (t < DD) {
        float mu = statsIn[t] * (1.f / NN);
        float var = statsIn[DD + t] * (1.f / NN) - mu * mu;
        float r = rsqrtf(var + 1e-5f);
        float sc = g[t] * r;
        esc[t] = sc;
        esh[t] = fmaf(-mu, sc, bt[t]);
    }
    __syncthreads();
    int node = blockIdx.x * 8 + w;
    int c4 = lane << 2;
    uint2 zh = *(const uint2*)(Z + (long)node * DD + c4);
    float2 p0 = h2f(zh.x), p1 = h2f(zh.y);
    float4 z = make_float4(p0.x, p0.y, p1.x, p1.y);
    z.x = fmaxf(fmaf(z.x, esc[c4 + 0], esh[c4 + 0]), 0.f);
    z.y = fmaxf(fmaf(z.y, esc[c4 + 1], esh[c4 + 1]), 0.f);
    z.z = fmaxf(fmaf(z.z, esc[c4 + 2], esh[c4 + 2]), 0.f);
    z.w = fmaxf(fmaf(z.w, esc[c4 + 3], esh[c4 + 3]), 0.f);
    *(uint2*)(d_Hb + (long)node * DD + c4) = f4_to_h4(z);
    *(float4*)&zbuf[w][c4] = z;
    if (lane == 0) bid[w] = d_is64 ? batch[2 * node] : batch[node];
    __syncthreads();
    int b = bid[w];
    bool leader = (w == 0) || (bid[w - 1] != b);
    if (leader) {
        float4 s = *(float4*)&zbuf[w][c4];
        for (int u = w + 1; u < 8 && bid[u] == b; u++) {
            float4 q = *(float4*)&zbuf[u][c4];
            s.x += q.x; s.y += q.y; s.z += q.z; s.w += q.w;
        }
        red4(d_readout + b * (NL * DD) + layer * DD + c4, s);
    }
}

__global__ void k_classifier(const float* __restrict__ Wc1, const float* __restrict__ bc1,
                             const float* __restrict__ Wc2, const float* __restrict__ bc2,
                             float* __restrict__ out) {
    int gidx = blockIdx.x;
    int t = threadIdx.x;
    __shared__ float red[NCLS];
    const float* r = d_readout + gidx * (NL * DD);
    float acc = bc1[t];
#pragma unroll 4
    for (int k = 0; k < NL * DD; k++) acc = fmaf(r[k], Wc1[k * DD + t], acc);
    float h = fmaxf(acc, 0.f);
    if (t < NCLS) red[t] = 0.f;
    __syncthreads();
#pragma unroll
    for (int c = 0; c < NCLS; c++) atomicAdd(&red[c], h * Wc2[t * NCLS + c]);
    __syncthreads();
    if (t < NCLS) out[gidx * NCLS + t] = red[t] + bc2[t];
}

// ---------------- launcher ----------------
extern "C" void kernel_launch(void* const* d_in, const int* in_sizes, int n_in,
                              void* d_out, int out_size) {
    const float* x   = (const float*)d_in[0];
    const int*   ei  = (const int*)d_in[1];
    const int*   bat = (const int*)d_in[2];
    const float* W1  = (const float*)d_in[3];
    const float* b1  = (const float*)d_in[4];
    const float* g1  = (const float*)d_in[5];
    const float* bt1 = (const float*)d_in[6];
    const float* W2  = (const float*)d_in[7];
    const float* b2  = (const float*)d_in[8];
    const float* g2  = (const float*)d_in[9];
    const float* bt2 = (const float*)d_in[10];
    const float* Wc1 = (const float*)d_in[11];
    const float* bc1 = (const float*)d_in[12];
    const float* Wc2 = (const float*)d_in[13];
    const float* bc2 = (const float*)d_in[14];
    float* out = (float*)d_out;

    float *pB, *pC, *pStats;
    unsigned short* pWt;
    cudaGetSymbolAddress((void**)&pB, d_B);
    cudaGetSymbolAddress((void**)&pC, d_C);
    cudaGetSymbolAddress((void**)&pStats, d_stats);
    cudaGetSymbolAddress((void**)&pWt, d_Wt);

    // one-time (first call is the uncaptured correctness run)
    static cudaStream_t sCSR = nullptr;
    static cudaEvent_t evFork = nullptr, evJoin = nullptr;
    if (!sCSR) {
        cudaStreamCreateWithFlags(&sCSR, cudaStreamNonBlocking);
        cudaEventCreateWithFlags(&evFork, cudaEventDisableTiming);
        cudaEventCreateWithFlags(&evJoin, cudaEventDisableTiming);
    }

    // setup: CSR chain on sCSR concurrent with prep on main
    cudaEventRecord(evFork, 0);
    cudaStreamWaitEvent(sCSR, evFork, 0);
    k_init<<<384, 256, 0, sCSR>>>(ei);
    k_hist<<<(NE + 255) / 256, 256, 0, sCSR>>>(ei);
    k_scan1<<<196, 256, 0, sCSR>>>();
    k_scan23<<<196, 256, 0, sCSR>>>();
    k_fill<<<(NE + 255) / 256, 256, 0, sCSR>>>(ei);
    cudaEventRecord(evJoin, sCSR);

    k_prep<<<6634, 256>>>(x, W1, W2);
    cudaStreamWaitEvent(0, evJoin, 0);   // join before the layer loop

    for (int L = 0; L < NL; L++) {
        float* s1 = pStats + (L * 2 + 0) * (2 * DD);
        float* s2 = pStats + (L * 2 + 1) * (2 * DD);
        k_agg<<<3125, 256>>>();
        k_gemm<0><<<M_TILES, 256>>>(pB, pWt + L * 32768, b1 + L * DD,
                                    nullptr, nullptr, nullptr, s1, pC);
        k_gemm<1><<<M_TILES, 256>>>(pC, pWt + (3 + L) * 32768, b2 + L * DD,
                                    g1 + L * DD, bt1 + L * DD, s1, s2, pB);
        k_epilogue<<<NN / 8, 256>>>((unsigned short*)pB, bat,
                                    g2 + L * DD, bt2 + L * DD, s2, L);
    }
    k_classifier<<<NG, 128>>>(Wc1, bc1, Wc2, bc2, out);
}

// round 14
// speedup vs baseline: 1.3938x; 1.1289x over previous
#include <cuda_runtime.h>
#include <cuda_bf16.h>
#include <cuda_fp16.h>

#define NN 50000
#define NE 800000
#define DD 128
#define NL 3
#define NG 256
#define NCLS 10
#define M_TILES 391   // ceil(50000/128)

// ---------------- scratch (static device globals; no allocation) ----------------
__device__ unsigned short d_Hb[NN * DD];     // h as fp16 (gather format)
__device__ float d_B[NN * DD];               // agg (fp32); z2 stored as fp16 in low half
__device__ float d_C[NN * DD];               // z1
__device__ float d_stats[NL * 2 * 2 * DD];   // per (layer, bn#): [sum | sumsq]
__device__ float d_readout[NG * NL * DD];
__device__ unsigned short d_Wt[6 * DD * DD]; // W transposed fp16: [mat][n][k]
__device__ int   d_deg[NN];
__device__ int   d_cur[NN];
__device__ int   d_off[NN + 1];
__device__ int   d_csr[NE];
__device__ int   d_bsum[256];
__device__ int   d_is64;

// ---------------- helpers ----------------
__device__ __forceinline__ void red4(float* p, float4 v) {
    asm volatile("red.global.add.v4.f32 [%0], {%1,%2,%3,%4};"
                 :: "l"(p), "f"(v.x), "f"(v.y), "f"(v.z), "f"(v.w) : "memory");
}
__device__ __forceinline__ unsigned smem_u32(const void* p) {
    unsigned r;
    asm("{ .reg .u64 t; cvta.to.shared.u64 t, %1; cvt.u32.u64 %0, t; }" : "=r"(r) : "l"(p));
    return r;
}
__device__ __forceinline__ void cpasync16(unsigned dst, const void* src) {
    asm volatile("cp.async.cg.shared.global [%0], [%1], 16;" :: "r"(dst), "l"(src));
}
__device__ __forceinline__ void mma16816h(float* d, const unsigned* a, const unsigned* b) {
    asm volatile("mma.sync.aligned.m16n8k16.row.col.f32.f16.f16.f32 "
                 "{%0,%1,%2,%3},{%4,%5,%6,%7},{%8,%9},{%0,%1,%2,%3};"
                 : "+f"(d[0]), "+f"(d[1]), "+f"(d[2]), "+f"(d[3])
                 : "r"(a[0]), "r"(a[1]), "r"(a[2]), "r"(a[3]), "r"(b[0]), "r"(b[1]));
}
__device__ __forceinline__ void ldsm4(unsigned* r, unsigned addr) {
    asm volatile("ldmatrix.sync.aligned.m8n8.x4.shared.b16 {%0,%1,%2,%3},[%4];"
                 : "=r"(r[0]), "=r"(r[1]), "=r"(r[2]), "=r"(r[3]) : "r"(addr));
}
__device__ __forceinline__ float2 h2f(unsigned u) {
    return __half22float2(*(__half2*)&u);
}
__device__ __forceinline__ unsigned f2_to_h2(float x, float y) {
    __half2 a = __floats2half2_rn(x, y);
    return *(unsigned*)&a;
}
__device__ __forceinline__ uint2 f4_to_h4(float4 v) {
    uint2 o; o.x = f2_to_h2(v.x, v.y); o.y = f2_to_h2(v.z, v.w);
    return o;
}
__device__ __forceinline__ void addrow(float4& a, uint2 v) {
    float2 p0 = h2f(v.x), p1 = h2f(v.y);
    a.x += p0.x; a.y += p0.y; a.z += p1.x; a.w += p1.y;
}

// ---------------- setup kernels ----------------

__global__ void k_init(const int* __restrict__ ei) {
    int i = blockIdx.x * 256 + threadIdx.x;
    if (i == 0) {
        int z = 1;
#pragma unroll
        for (int k = 1; k < 256; k += 2) z &= (ei[k] == 0);
        d_is64 = z;
    }
    if (i < NG * NL * DD) d_readout[i] = 0.f;
    if (i < NL * 2 * 2 * DD) d_stats[i] = 0.f;
    if (i < NN) d_deg[i] = 0;
}

// x -> fp16 Hb; W -> transposed fp16 planes
__global__ void k_prep(const float* __restrict__ x,
                       const float* __restrict__ W1, const float* __restrict__ W2) {
    if (blockIdx.x < 6250) {
        int i = blockIdx.x * 256 + threadIdx.x;      // NN*32 = 1.6M
        float4 v = ((const float4*)x)[i];
        ((uint2*)d_Hb)[i] = f4_to_h4(v);
    } else {
        int id = (blockIdx.x - 6250) * 256 + threadIdx.x;  // 6*16384
        int mat = id >> 14;
        int r = id & 16383;
        int n = r & 127, k = r >> 7;
        const float* src = (mat < 3) ? (W1 + mat * 16384) : (W2 + (mat - 3) * 16384);
        d_Wt[mat * 16384 + n * DD + k] =
            __half_as_ushort(__float2half_rn(src[k * DD + n]));
    }
}

__global__ void k_hist(const int* __restrict__ ei) {
    int e = blockIdx.x * 256 + threadIdx.x;
    if (e >= NE) return;
    int dst = d_is64 ? ei[2 * (NE + e)] : ei[NE + e];
    atomicAdd(&d_deg[dst], 1);
}

__global__ void k_scan1() {
    __shared__ int s[256];
    int t = threadIdx.x;
    int i = blockIdx.x * 256 + t;
    int v = (i < NN) ? d_deg[i] : 0;
    s[t] = v;
    __syncthreads();
#pragma unroll
    for (int d = 1; d < 256; d <<= 1) {
        int x = (t >= d) ? s[t - d] : 0;
        __syncthreads();
        s[t] += x;
        __syncthreads();
    }
    if (i < NN) d_off[i + 1] = s[t];
    if (t == 255) d_bsum[blockIdx.x] = s[255];
}

__global__ void k_scan23() {
    __shared__ int s[256];
    int t = threadIdx.x;
    s[t] = (t < 196) ? d_bsum[t] : 0;
    __syncthreads();
#pragma unroll
    for (int d = 1; d < 256; d <<= 1) {
        int x = (t >= d) ? s[t - d] : 0;
        __syncthreads();
        s[t] += x;
        __syncthreads();
    }
    int b = blockIdx.x;
    int pre = (b == 0) ? 0 : s[b - 1];
    int i = b * 256 + t;
    if (i < NN) { d_off[i + 1] += pre; d_cur[i] = 0; }
    if (i == 0) d_off[0] = 0;
}

__global__ void k_fill(const int* __restrict__ ei) {
    int e = blockIdx.x * 256 + threadIdx.x;
    if (e >= NE) return;
    int src, dst;
    if (d_is64) { src = ei[2 * e]; dst = ei[2 * (NE + e)]; }
    else        { src = ei[e];     dst = ei[NE + e]; }
    int p = atomicAdd(&d_cur[dst], 1);
    d_csr[d_off[dst] + p] = src;
}

// One warp per TWO nodes: full-warp uint2 gather (256B row), joint 4+4 loop.
__global__ void k_agg() {
    int w = (blockIdx.x * 256 + threadIdx.x) >> 5;
    int n0 = 2 * w, n1 = 2 * w + 1;
    if (n0 >= NN) return;
    int lane = threadIdx.x & 31;
    const uint2* hv = (const uint2*)d_Hb;
    float4 aA, aB;
    { uint2 v = __ldg(&hv[(long)n0 * 32 + lane]); float2 p0 = h2f(v.x), p1 = h2f(v.y);
      aA = make_float4(p0.x, p0.y, p1.x, p1.y); }
    { uint2 v = __ldg(&hv[(long)n1 * 32 + lane]); float2 p0 = h2f(v.x), p1 = h2f(v.y);
      aB = make_float4(p0.x, p0.y, p1.x, p1.y); }
    int j0 = d_off[n0], e0 = d_off[n0 + 1];
    int j1 = e0,        e1 = d_off[n1 + 1];
    while (j0 + 4 <= e0 && j1 + 4 <= e1) {
        int s00 = d_csr[j0], s01 = d_csr[j0 + 1], s02 = d_csr[j0 + 2], s03 = d_csr[j0 + 3];
        int s10 = d_csr[j1], s11 = d_csr[j1 + 1], s12 = d_csr[j1 + 2], s13 = d_csr[j1 + 3];
        uint2 v00 = __ldg(&hv[(long)s00 * 32 + lane]);
        uint2 v01 = __ldg(&hv[(long)s01 * 32 + lane]);
        uint2 v02 = __ldg(&hv[(long)s02 * 32 + lane]);
        uint2 v03 = __ldg(&hv[(long)s03 * 32 + lane]);
        uint2 v10 = __ldg(&hv[(long)s10 * 32 + lane]);
        uint2 v11 = __ldg(&hv[(long)s11 * 32 + lane]);
        uint2 v12 = __ldg(&hv[(long)s12 * 32 + lane]);
        uint2 v13 = __ldg(&hv[(long)s13 * 32 + lane]);
        addrow(aA, v00); addrow(aA, v01); addrow(aA, v02); addrow(aA, v03);
        addrow(aB, v10); addrow(aB, v11); addrow(aB, v12); addrow(aB, v13);
        j0 += 4; j1 += 4;
    }
    for (; j0 + 4 <= e0; j0 += 4) {
        int s0 = d_csr[j0], s1 = d_csr[j0 + 1], s2 = d_csr[j0 + 2], s3 = d_csr[j0 + 3];
        uint2 v0 = __ldg(&hv[(long)s0 * 32 + lane]);
        uint2 v1 = __ldg(&hv[(long)s1 * 32 + lane]);
        uint2 v2 = __ldg(&hv[(long)s2 * 32 + lane]);
        uint2 v3 = __ldg(&hv[(long)s3 * 32 + lane]);
        addrow(aA, v0); addrow(aA, v1); addrow(aA, v2); addrow(aA, v3);
    }
    for (; j0 < e0; j0++) addrow(aA, __ldg(&hv[(long)d_csr[j0] * 32 + lane]));
    for (; j1 + 4 <= e1; j1 += 4) {
        int s0 = d_csr[j1], s1 = d_csr[j1 + 1], s2 = d_csr[j1 + 2], s3 = d_csr[j1 + 3];
        uint2 v0 = __ldg(&hv[(long)s0 * 32 + lane]);
        uint2 v1 = __ldg(&hv[(long)s1 * 32 + lane]);
        uint2 v2 = __ldg(&hv[(long)s2 * 32 + lane]);
        uint2 v3 = __ldg(&hv[(long)s3 * 32 + lane]);
        addrow(aB, v0); addrow(aB, v1); addrow(aB, v2); addrow(aB, v3);
    }
    for (; j1 < e1; j1++) addrow(aB, __ldg(&hv[(long)d_csr[j1] * 32 + lane]));
    ((float4*)d_B)[(long)n0 * 32 + lane] = aA;
    ((float4*)d_B)[(long)n1 * 32 + lane] = aB;
}

// ---------------- tensor-core GEMM (single-pass fp16 MMA, fp32 accum) --------
// MODE 0: f = identity, fp32 out (z1). MODE 1: f = relu(P*sc+sh), fp16 out (z2).
// smem: A fp16 [128r x 32k] @80B pitch (10240), W fp16 [128n x 32k] (10240).
template <int MODE>
__global__ void __launch_bounds__(256, 2)
k_gemm(const float* __restrict__ P, const unsigned short* __restrict__ Wt,
       const float* __restrict__ bias,
       const float* __restrict__ g, const float* __restrict__ bt,
       const float* __restrict__ statsIn, float* __restrict__ statsOut,
       float* __restrict__ out) {
    __shared__ __align__(16) unsigned char sm[20480];
    unsigned sbase = smem_u32(sm);
    const unsigned WHI = 10240;

    int t = threadIdx.x;
    int lane = t & 31, wid = t >> 5;
    int wm = wid & 3, wn = wid >> 2;
    int m0w = wm * 32, n0w = wn * 64;
    int row0 = blockIdx.x * 128;
    int kc = (t & 7) << 2;

    // prologue: W chunk0
#pragma unroll
    for (int i = 0; i < 2; i++) {
        int id = t + i * 256;                 // 0..511
        int n = id >> 2, q = id & 3;
        cpasync16(sbase + WHI + (unsigned)(n * 80 + q * 16), Wt + n * DD + q * 8);
    }
    asm volatile("cp.async.commit_group;");

    float4 pa[4];
#pragma unroll
    for (int i = 0; i < 4; i++) {
        int row = (t + i * 256) >> 3;
        int gr = row0 + row;
        pa[i] = (gr < NN) ? *(const float4*)(P + (long)gr * DD + kc)
                          : make_float4(0.f, 0.f, 0.f, 0.f);
    }

    float acc[2][8][4];
#pragma unroll
    for (int ni = 0; ni < 8; ni++) {
        int c0 = n0w + 8 * ni + 2 * (lane & 3);
        float b0 = bias[c0], b1 = bias[c0 + 1];
#pragma unroll
        for (int mi = 0; mi < 2; mi++) {
            acc[mi][ni][0] = b0; acc[mi][ni][1] = b1;
            acc[mi][ni][2] = b0; acc[mi][ni][3] = b1;
        }
    }

    for (int c = 0; c < 4; c++) {
        int kk = c * 32;
        float4 sc4, sh4;
        if (MODE == 1) {
            int c0 = kk + kc;
            float4 smv = *(const float4*)(statsIn + c0);
            float4 sq = *(const float4*)(statsIn + DD + c0);
            float4 gv = *(const float4*)(g + c0);
            float4 bv = *(const float4*)(bt + c0);
            float mu, var, r;
            mu = smv.x * (1.f / NN); var = sq.x * (1.f / NN) - mu * mu;
            r = rsqrtf(var + 1e-5f); sc4.x = gv.x * r; sh4.x = fmaf(-mu, sc4.x, bv.x);
            mu = smv.y * (1.f / NN); var = sq.y * (1.f / NN) - mu * mu;
            r = rsqrtf(var + 1e-5f); sc4.y = gv.y * r; sh4.y = fmaf(-mu, sc4.y, bv.y);
            mu = smv.z * (1.f / NN); var = sq.z * (1.f / NN) - mu * mu;
            r = rsqrtf(var + 1e-5f); sc4.z = gv.z * r; sh4.z = fmaf(-mu, sc4.z, bv.z);
            mu = smv.w * (1.f / NN); var = sq.w * (1.f / NN) - mu * mu;
            r = rsqrtf(var + 1e-5f); sc4.w = gv.w * r; sh4.w = fmaf(-mu, sc4.w, bv.w);
        }

        // STS A as fp16 (transform in fp32 first)
#pragma unroll
        for (int i = 0; i < 4; i++) {
            int row = (t + i * 256) >> 3;
            float4 v = pa[i];
            if (MODE == 1) {
                v.x = fmaxf(fmaf(v.x, sc4.x, sh4.x), 0.f);
                v.y = fmaxf(fmaf(v.y, sc4.y, sh4.y), 0.f);
                v.z = fmaxf(fmaf(v.z, sc4.z, sh4.z), 0.f);
                v.w = fmaxf(fmaf(v.w, sc4.w, sh4.w), 0.f);
            }
            unsigned off = (unsigned)(row * 80 + kc * 2);
            *(unsigned*)(sm + off) = f2_to_h2(v.x, v.y);
            *(unsigned*)(sm + off + 4) = f2_to_h2(v.z, v.w);
        }

        if (c < 3) {
#pragma unroll
            for (int i = 0; i < 4; i++) {
                int row = (t + i * 256) >> 3;
                int gr = row0 + row;
                pa[i] = (gr < NN) ? *(const float4*)(P + (long)gr * DD + kk + 32 + kc)
                                  : make_float4(0.f, 0.f, 0.f, 0.f);
            }
        }

        asm volatile("cp.async.wait_group 0;");
        __syncthreads();

#pragma unroll
        for (int ks = 0; ks < 2; ks++) {
            int kb = ks * 16;
            unsigned ah[2][4];
#pragma unroll
            for (int mi = 0; mi < 2; mi++) {
                unsigned ad = sbase
                    + (unsigned)((m0w + 16 * mi + (lane & 7) + ((lane >> 3) & 1) * 8) * 80
                                 + (kb + (lane >> 4) * 8) * 2);
                ldsm4(ah[mi], ad);
            }
#pragma unroll
            for (int q = 0; q < 4; q++) {
                unsigned bd = sbase + WHI
                    + (unsigned)((n0w + 16 * q + ((lane >> 4) & 1) * 8 + (lane & 7)) * 80
                                 + (kb + ((lane >> 3) & 1) * 8) * 2);
                unsigned bh[4];
                ldsm4(bh, bd);
#pragma unroll
                for (int mi = 0; mi < 2; mi++) {
#pragma unroll
                    for (int s = 0; s < 2; s++) {
                        mma16816h(acc[mi][2 * q + s], ah[mi], bh + 2 * s);
                    }
                }
            }
        }
        __syncthreads();

        if (c < 3) {
#pragma unroll
            for (int i = 0; i < 2; i++) {
                int id = t + i * 256;
                int n = id >> 2, q = id & 3;
                cpasync16(sbase + WHI + (unsigned)(n * 80 + q * 16),
                          Wt + n * DD + (kk + 32) + q * 8);
            }
            asm volatile("cp.async.commit_group;");
        }
    }

    // ---- epilogue: store output + fused BN column stats ----
    float* Sa = (float*)sm;            // [4][128]
    float* Sq = (float*)(sm + 2048);   // [4][128]
    unsigned short* outh = (unsigned short*)out;
#pragma unroll
    for (int ni = 0; ni < 8; ni++) {
        int c0 = n0w + 8 * ni + 2 * (lane & 3);
        float s0 = 0.f, q0 = 0.f, s1 = 0.f, q1 = 0.f;
#pragma unroll
        for (int mi = 0; mi < 2; mi++) {
            int r0 = row0 + m0w + 16 * mi + (lane >> 2);
            int r1 = r0 + 8;
            float v0 = acc[mi][ni][0], v1 = acc[mi][ni][1];
            float v2 = acc[mi][ni][2], v3 = acc[mi][ni][3];
            if (r0 < NN) {
                if (MODE == 1)
                    *(unsigned*)(outh + (long)r0 * DD + c0) = f2_to_h2(v0, v1);
                else
                    *(float2*)(out + (long)r0 * DD + c0) = make_float2(v0, v1);
                s0 += v0; q0 = fmaf(v0, v0, q0);
                s1 += v1; q1 = fmaf(v1, v1, q1);
            }
            if (r1 < NN) {
                if (MODE == 1)
                    *(unsigned*)(outh + (long)r1 * DD + c0) = f2_to_h2(v2, v3);
                else
                    *(float2*)(out + (long)r1 * DD + c0) = make_float2(v2, v3);
                s0 += v2; q0 = fmaf(v2, v2, q0);
                s1 += v3; q1 = fmaf(v3, v3, q1);
            }
        }
#pragma unroll
        for (int m = 4; m <= 16; m <<= 1) {
            s0 += __shfl_xor_sync(0xffffffffu, s0, m);
            q0 += __shfl_xor_sync(0xffffffffu, q0, m);
            s1 += __shfl_xor_sync(0xffffffffu, s1, m);
            q1 += __shfl_xor_sync(0xffffffffu, q1, m);
        }
        if (lane < 4) {
            int cc = n0w + 8 * ni + 2 * lane;
            Sa[wm * 128 + cc] = s0; Sa[wm * 128 + cc + 1] = s1;
            Sq[wm * 128 + cc] = q0; Sq[wm * 128 + cc + 1] = q1;
        }
    }
    __syncthreads();
    if (t < 128) {
        float S = Sa[t] + Sa[128 + t] + Sa[256 + t] + Sa[384 + t];
        float Q = Sq[t] + Sq[128 + t] + Sq[256 + t] + Sq[384 + t];
        atomicAdd(&statsOut[t], S);
        atomicAdd(&statsOut[DD + t], Q);
    }
}

// Final BN+ReLU: read fp16 z2, write fp16 h; merge readout runs (batch sorted).
__global__ void k_epilogue(const unsigned short* __restrict__ Z, const int* __restrict__ batch,
                           const float* __restrict__ g, const float* __restrict__ bt,
                           const float* __restrict__ statsIn, int layer) {
    __shared__ float esc[DD], esh[DD];
    __shared__ float zbuf[8][DD];
    __shared__ int bid[8];
    int t = threadIdx.x;
    int w = t >> 5, lane = t & 31;
    if (t < DD) {
        float mu = statsIn[t] * (1.f / NN);
        float var = statsIn[DD + t] * (1.f / NN) - mu * mu;
        float r = rsqrtf(var + 1e-5f);
        float sc = g[t] * r;
        esc[t] = sc;
        esh[t] = fmaf(-mu, sc, bt[t]);
    }
    __syncthreads();
    int node = blockIdx.x * 8 + w;
    int c4 = lane << 2;
    uint2 zh = *(const uint2*)(Z + (long)node * DD + c4);
    float2 p0 = h2f(zh.x), p1 = h2f(zh.y);
    float4 z = make_float4(p0.x, p0.y, p1.x, p1.y);
    z.x = fmaxf(fmaf(z.x, esc[c4 + 0], esh[c4 + 0]), 0.f);
    z.y = fmaxf(fmaf(z.y, esc[c4 + 1], esh[c4 + 1]), 0.f);
    z.z = fmaxf(fmaf(z.z, esc[c4 + 2], esh[c4 + 2]), 0.f);
    z.w = fmaxf(fmaf(z.w, esc[c4 + 3], esh[c4 + 3]), 0.f);
    *(uint2*)(d_Hb + (long)node * DD + c4) = f4_to_h4(z);
    *(float4*)&zbuf[w][c4] = z;
    if (lane == 0) bid[w] = d_is64 ? batch[2 * node] : batch[node];
    __syncthreads();
    int b = bid[w];
    bool leader = (w == 0) || (bid[w - 1] != b);
    if (leader) {
        float4 s = *(float4*)&zbuf[w][c4];
        for (int u = w + 1; u < 8 && bid[u] == b; u++) {
            float4 q = *(float4*)&zbuf[u][c4];
            s.x += q.x; s.y += q.y; s.z += q.z; s.w += q.w;
        }
        red4(d_readout + b * (NL * DD) + layer * DD + c4, s);
    }
}

__global__ void k_classifier(const float* __restrict__ Wc1, const float* __restrict__ bc1,
                             const float* __restrict__ Wc2, const float* __restrict__ bc2,
                             float* __restrict__ out) {
    int gidx = blockIdx.x;
    int t = threadIdx.x;
    __shared__ float red[NCLS];
    const float* r = d_readout + gidx * (NL * DD);
    float acc = bc1[t];
#pragma unroll 4
    for (int k = 0; k < NL * DD; k++) acc = fmaf(r[k], Wc1[k * DD + t], acc);
    float h = fmaxf(acc, 0.f);
    if (t < NCLS) red[t] = 0.f;
    __syncthreads();
#pragma unroll
    for (int c = 0; c < NCLS; c++) atomicAdd(&red[c], h * Wc2[t * NCLS + c]);
    __syncthreads();
    if (t < NCLS) out[gidx * NCLS + t] = red[t] + bc2[t];
}

// ---------------- launcher ----------------
extern "C" void kernel_launch(void* const* d_in, const int* in_sizes, int n_in,
                              void* d_out, int out_size) {
    const float* x   = (const float*)d_in[0];
    const int*   ei  = (const int*)d_in[1];
    const int*   bat = (const int*)d_in[2];
    const float* W1  = (const float*)d_in[3];
    const float* b1  = (const float*)d_in[4];
    const float* g1  = (const float*)d_in[5];
    const float* bt1 = (const float*)d_in[6];
    const float* W2  = (const float*)d_in[7];
    const float* b2  = (const float*)d_in[8];
    const float* g2  = (const float*)d_in[9];
    const float* bt2 = (const float*)d_in[10];
    const float* Wc1 = (const float*)d_in[11];
    const float* bc1 = (const float*)d_in[12];
    const float* Wc2 = (const float*)d_in[13];
    const float* bc2 = (const float*)d_in[14];
    float* out = (float*)d_out;

    float *pB, *pC, *pStats;
    unsigned short* pWt;
    cudaGetSymbolAddress((void**)&pB, d_B);
    cudaGetSymbolAddress((void**)&pC, d_C);
    cudaGetSymbolAddress((void**)&pStats, d_stats);
    cudaGetSymbolAddress((void**)&pWt, d_Wt);

    // one-time (first call is the uncaptured correctness run)
    static cudaStream_t sCSR = nullptr;
    static cudaEvent_t evFork = nullptr, evJoin = nullptr;
    if (!sCSR) {
        cudaStreamCreateWithFlags(&sCSR, cudaStreamNonBlocking);
        cudaEventCreateWithFlags(&evFork, cudaEventDisableTiming);
        cudaEventCreateWithFlags(&evJoin, cudaEventDisableTiming);
    }

    // setup: CSR chain on sCSR concurrent with prep on main
    cudaEventRecord(evFork, 0);
    cudaStreamWaitEvent(sCSR, evFork, 0);
    k_init<<<384, 256, 0, sCSR>>>(ei);
    k_hist<<<(NE + 255) / 256, 256, 0, sCSR>>>(ei);
    k_scan1<<<196, 256, 0, sCSR>>>();
    k_scan23<<<196, 256, 0, sCSR>>>();
    k_fill<<<(NE + 255) / 256, 256, 0, sCSR>>>(ei);
    cudaEventRecord(evJoin, sCSR);

    k_prep<<<6634, 256>>>(x, W1, W2);
    cudaStreamWaitEvent(0, evJoin, 0);   // join before the layer loop

    for (int L = 0; L < NL; L++) {
        float* s1 = pStats + (L * 2 + 0) * (2 * DD);
        float* s2 = pStats + (L * 2 + 1) * (2 * DD);
        k_agg<<<3125, 256>>>();
        k_gemm<0><<<M_TILES, 256>>>(pB, pWt + L * 16384, b1 + L * DD,
                                    nullptr, nullptr, nullptr, s1, pC);
        k_gemm<1><<<M_TILES, 256>>>(pC, pWt + (3 + L) * 16384, b2 + L * DD,
                                    g1 + L * DD, bt1 + L * DD, s1, s2, pB);
        k_epilogue<<<NN / 8, 256>>>((unsigned short*)pB, bat,
                                    g2 + L * DD, bt2 + L * DD, s2, L);
    }
    k_classifier<<<NG, 128>>>(Wc1, bc1, Wc2, bc2, out);
}

// round 16
// speedup vs baseline: 1.4113x; 1.0126x over previous
#include <cuda_runtime.h>
#include <cuda_bf16.h>
#include <cuda_fp16.h>

#define NN 50000
#define NE 800000
#define DD 128
#define NL 3
#define NG 256
#define NCLS 10
#define M_TILES 391   // ceil(50000/128)

// ---------------- scratch (static device globals; no allocation) ----------------
__device__ unsigned short d_Hb[NN * DD];     // h as fp16 (gather format)
__device__ float d_B[NN * DD];               // agg (fp16 in low half); z2 (fp16) later
__device__ float d_C[NN * DD];               // z1 (fp32)
__device__ float d_stats[NL * 2 * 2 * DD];   // per (layer, bn#): [sum | sumsq]
__device__ float d_readout[NG * NL * DD];
__device__ unsigned short d_Wt[6 * DD * DD]; // W transposed fp16: [mat][n][k]
__device__ int   d_deg[NN];
__device__ int   d_cur[NN];
__device__ int   d_off[NN + 1];
__device__ int   d_csr[NE];
__device__ int   d_bsum[256];
__device__ int   d_is64;

// ---------------- helpers ----------------
__device__ __forceinline__ void red4(float* p, float4 v) {
    asm volatile("red.global.add.v4.f32 [%0], {%1,%2,%3,%4};"
                 :: "l"(p), "f"(v.x), "f"(v.y), "f"(v.z), "f"(v.w) : "memory");
}
__device__ __forceinline__ unsigned smem_u32(const void* p) {
    unsigned r;
    asm("{ .reg .u64 t; cvta.to.shared.u64 t, %1; cvt.u32.u64 %0, t; }" : "=r"(r) : "l"(p));
    return r;
}
__device__ __forceinline__ void cpasync16(unsigned dst, const void* src) {
    asm volatile("cp.async.cg.shared.global [%0], [%1], 16;" :: "r"(dst), "l"(src));
}
__device__ __forceinline__ void mma16816h(float* d, const unsigned* a, const unsigned* b) {
    asm volatile("mma.sync.aligned.m16n8k16.row.col.f32.f16.f16.f32 "
                 "{%0,%1,%2,%3},{%4,%5,%6,%7},{%8,%9},{%0,%1,%2,%3};"
                 : "+f"(d[0]), "+f"(d[1]), "+f"(d[2]), "+f"(d[3])
                 : "r"(a[0]), "r"(a[1]), "r"(a[2]), "r"(a[3]), "r"(b[0]), "r"(b[1]));
}
__device__ __forceinline__ void ldsm4(unsigned* r, unsigned addr) {
    asm volatile("ldmatrix.sync.aligned.m8n8.x4.shared.b16 {%0,%1,%2,%3},[%4];"
                 : "=r"(r[0]), "=r"(r[1]), "=r"(r[2]), "=r"(r[3]) : "r"(addr));
}
__device__ __forceinline__ float2 h2f(unsigned u) {
    return __half22float2(*(__half2*)&u);
}
__device__ __forceinline__ unsigned f2_to_h2(float x, float y) {
    __half2 a = __floats2half2_rn(x, y);
    return *(unsigned*)&a;
}
__device__ __forceinline__ uint2 f4_to_h4(float4 v) {
    uint2 o; o.x = f2_to_h2(v.x, v.y); o.y = f2_to_h2(v.z, v.w);
    return o;
}
__device__ __forceinline__ void addrow(float4& a, uint2 v) {
    float2 p0 = h2f(v.x), p1 = h2f(v.y);
    a.x += p0.x; a.y += p0.y; a.z += p1.x; a.w += p1.y;
}

// ---------------- setup kernels ----------------

__global__ void k_init(const int* __restrict__ ei) {
    int i = blockIdx.x * 256 + threadIdx.x;
    if (i == 0) {
        int z = 1;
#pragma unroll
        for (int k = 1; k < 256; k += 2) z &= (ei[k] == 0);
        d_is64 = z;
    }
    if (i < NG * NL * DD) d_readout[i] = 0.f;
    if (i < NL * 2 * 2 * DD) d_stats[i] = 0.f;
    if (i < NN) d_deg[i] = 0;
}

// x -> fp16 Hb; W -> transposed fp16 planes
__global__ void k_prep(const float* __restrict__ x,
                       const float* __restrict__ W1, const float* __restrict__ W2) {
    if (blockIdx.x < 6250) {
        int i = blockIdx.x * 256 + threadIdx.x;      // NN*32 = 1.6M
        float4 v = ((const float4*)x)[i];
        ((uint2*)d_Hb)[i] = f4_to_h4(v);
    } else {
        int id = (blockIdx.x - 6250) * 256 + threadIdx.x;  // 6*16384
        int mat = id >> 14;
        int r = id & 16383;
        int n = r & 127, k = r >> 7;
        const float* src = (mat < 3) ? (W1 + mat * 16384) : (W2 + (mat - 3) * 16384);
        d_Wt[mat * 16384 + n * DD + k] =
            __half_as_ushort(__float2half_rn(src[k * DD + n]));
    }
}

__global__ void k_hist(const int* __restrict__ ei) {
    int e = blockIdx.x * 256 + threadIdx.x;
    if (e >= NE) return;
    int dst = d_is64 ? ei[2 * (NE + e)] : ei[NE + e];
    atomicAdd(&d_deg[dst], 1);
}

__global__ void k_scan1() {
    __shared__ int s[256];
    int t = threadIdx.x;
    int i = blockIdx.x * 256 + t;
    int v = (i < NN) ? d_deg[i] : 0;
    s[t] = v;
    __syncthreads();
#pragma unroll
    for (int d = 1; d < 256; d <<= 1) {
        int x = (t >= d) ? s[t - d] : 0;
        __syncthreads();
        s[t] += x;
        __syncthreads();
    }
    if (i < NN) d_off[i + 1] = s[t];
    if (t == 255) d_bsum[blockIdx.x] = s[255];
}

__global__ void k_scan23() {
    __shared__ int s[256];
    int t = threadIdx.x;
    s[t] = (t < 196) ? d_bsum[t] : 0;
    __syncthreads();
#pragma unroll
    for (int d = 1; d < 256; d <<= 1) {
        int x = (t >= d) ? s[t - d] : 0;
        __syncthreads();
        s[t] += x;
        __syncthreads();
    }
    int b = blockIdx.x;
    int pre = (b == 0) ? 0 : s[b - 1];
    int i = b * 256 + t;
    if (i < NN) { d_off[i + 1] += pre; d_cur[i] = 0; }
    if (i == 0) d_off[0] = 0;
}

__global__ void k_fill(const int* __restrict__ ei) {
    int e = blockIdx.x * 256 + threadIdx.x;
    if (e >= NE) return;
    int src, dst;
    if (d_is64) { src = ei[2 * e]; dst = ei[2 * (NE + e)]; }
    else        { src = ei[e];     dst = ei[NE + e]; }
    int p = atomicAdd(&d_cur[dst], 1);
    d_csr[d_off[dst] + p] = src;
}

// One warp per TWO nodes: full-warp uint2 gather; OUTPUT fp16 (coalesced uint2).
__global__ void k_agg() {
    int w = (blockIdx.x * 256 + threadIdx.x) >> 5;
    int n0 = 2 * w, n1 = 2 * w + 1;
    if (n0 >= NN) return;
    int lane = threadIdx.x & 31;
    const uint2* hv = (const uint2*)d_Hb;
    float4 aA, aB;
    { uint2 v = __ldg(&hv[(long)n0 * 32 + lane]); float2 p0 = h2f(v.x), p1 = h2f(v.y);
      aA = make_float4(p0.x, p0.y, p1.x, p1.y); }
    { uint2 v = __ldg(&hv[(long)n1 * 32 + lane]); float2 p0 = h2f(v.x), p1 = h2f(v.y);
      aB = make_float4(p0.x, p0.y, p1.x, p1.y); }
    int j0 = d_off[n0], e0 = d_off[n0 + 1];
    int j1 = e0,        e1 = d_off[n1 + 1];
    while (j0 + 4 <= e0 && j1 + 4 <= e1) {
        int s00 = d_csr[j0], s01 = d_csr[j0 + 1], s02 = d_csr[j0 + 2], s03 = d_csr[j0 + 3];
        int s10 = d_csr[j1], s11 = d_csr[j1 + 1], s12 = d_csr[j1 + 2], s13 = d_csr[j1 + 3];
        uint2 v00 = __ldg(&hv[(long)s00 * 32 + lane]);
        uint2 v01 = __ldg(&hv[(long)s01 * 32 + lane]);
        uint2 v02 = __ldg(&hv[(long)s02 * 32 + lane]);
        uint2 v03 = __ldg(&hv[(long)s03 * 32 + lane]);
        uint2 v10 = __ldg(&hv[(long)s10 * 32 + lane]);
        uint2 v11 = __ldg(&hv[(long)s11 * 32 + lane]);
        uint2 v12 = __ldg(&hv[(long)s12 * 32 + lane]);
        uint2 v13 = __ldg(&hv[(long)s13 * 32 + lane]);
        addrow(aA, v00); addrow(aA, v01); addrow(aA, v02); addrow(aA, v03);
        addrow(aB, v10); addrow(aB, v11); addrow(aB, v12); addrow(aB, v13);
        j0 += 4; j1 += 4;
    }
    for (; j0 + 4 <= e0; j0 += 4) {
        int s0 = d_csr[j0], s1 = d_csr[j0 + 1], s2 = d_csr[j0 + 2], s3 = d_csr[j0 + 3];
        uint2 v0 = __ldg(&hv[(long)s0 * 32 + lane]);
        uint2 v1 = __ldg(&hv[(long)s1 * 32 + lane]);
        uint2 v2 = __ldg(&hv[(long)s2 * 32 + lane]);
        uint2 v3 = __ldg(&hv[(long)s3 * 32 + lane]);
        addrow(aA, v0); addrow(aA, v1); addrow(aA, v2); addrow(aA, v3);
    }
    for (; j0 < e0; j0++) addrow(aA, __ldg(&hv[(long)d_csr[j0] * 32 + lane]));
    for (; j1 + 4 <= e1; j1 += 4) {
        int s0 = d_csr[j1], s1 = d_csr[j1 + 1], s2 = d_csr[j1 + 2], s3 = d_csr[j1 + 3];
        uint2 v0 = __ldg(&hv[(long)s0 * 32 + lane]);
        uint2 v1 = __ldg(&hv[(long)s1 * 32 + lane]);
        uint2 v2 = __ldg(&hv[(long)s2 * 32 + lane]);
        uint2 v3 = __ldg(&hv[(long)s3 * 32 + lane]);
        addrow(aB, v0); addrow(aB, v1); addrow(aB, v2); addrow(aB, v3);
    }
    for (; j1 < e1; j1++) addrow(aB, __ldg(&hv[(long)d_csr[j1] * 32 + lane]));
    ((uint2*)d_B)[(long)n0 * 32 + lane] = f4_to_h4(aA);
    ((uint2*)d_B)[(long)n1 * 32 + lane] = f4_to_h4(aB);
}

// ---------------- GEMM0: z1 = agg(fp16) @ W1 + b1, fused BN stats -----------
// Full cp.async pipeline for BOTH A and W. smem: A[2]x10240 + W[2]x10240.
__global__ void __launch_bounds__(256, 2)
k_gemm0(const unsigned short* __restrict__ A, const unsigned short* __restrict__ Wt,
        const float* __restrict__ bias, float* __restrict__ statsOut,
        float* __restrict__ out) {
    __shared__ __align__(16) unsigned char sm[40960];
    unsigned sbase = smem_u32(sm);

    int t = threadIdx.x;
    int lane = t & 31, wid = t >> 5;
    int wm = wid & 3, wn = wid >> 2;
    int m0w = wm * 32, n0w = wn * 64;
    int row0 = blockIdx.x * 128;

    // prologue: chunk 0 into buffer 0
    {
        unsigned ab = sbase, wb = sbase + 20480u;
#pragma unroll
        for (int i = 0; i < 2; i++) {
            int id = t + i * 256;
            int r = id >> 2, q = id & 3;
            cpasync16(ab + (unsigned)(r * 80 + q * 16), A + (long)(row0 + r) * DD + q * 8);
            cpasync16(wb + (unsigned)(r * 80 + q * 16), Wt + r * DD + q * 8);
        }
        asm volatile("cp.async.commit_group;");
    }

    float acc[2][8][4];
#pragma unroll
    for (int ni = 0; ni < 8; ni++) {
        int c0 = n0w + 8 * ni + 2 * (lane & 3);
        float b0 = bias[c0], b1 = bias[c0 + 1];
#pragma unroll
        for (int mi = 0; mi < 2; mi++) {
            acc[mi][ni][0] = b0; acc[mi][ni][1] = b1;
            acc[mi][ni][2] = b0; acc[mi][ni][3] = b1;
        }
    }

    for (int c = 0; c < 4; c++) {
        if (c < 3) {
            int nb = (c + 1) & 1;
            unsigned ab = sbase + nb * 10240u, wb = sbase + 20480u + nb * 10240u;
            int kk2 = (c + 1) * 32;
#pragma unroll
            for (int i = 0; i < 2; i++) {
                int id = t + i * 256;
                int r = id >> 2, q = id & 3;
                cpasync16(ab + (unsigned)(r * 80 + q * 16),
                          A + (long)(row0 + r) * DD + kk2 + q * 8);
                cpasync16(wb + (unsigned)(r * 80 + q * 16), Wt + r * DD + kk2 + q * 8);
            }
            asm volatile("cp.async.commit_group;");
            asm volatile("cp.async.wait_group 1;");
        } else {
            asm volatile("cp.async.wait_group 0;");
        }
        __syncthreads();

        unsigned abase = sbase + (c & 1) * 10240u;
        unsigned wbase = sbase + 20480u + (c & 1) * 10240u;
#pragma unroll
        for (int ks = 0; ks < 2; ks++) {
            int kb = ks * 16;
            unsigned ah[2][4];
#pragma unroll
            for (int mi = 0; mi < 2; mi++) {
                unsigned ad = abase
                    + (unsigned)((m0w + 16 * mi + (lane & 7) + ((lane >> 3) & 1) * 8) * 80
                                 + (kb + (lane >> 4) * 8) * 2);
                ldsm4(ah[mi], ad);
            }
#pragma unroll
            for (int q = 0; q < 4; q++) {
                unsigned bd = wbase
                    + (unsigned)((n0w + 16 * q + ((lane >> 4) & 1) * 8 + (lane & 7)) * 80
                                 + (kb + ((lane >> 3) & 1) * 8) * 2);
                unsigned bh[4];
                ldsm4(bh, bd);
#pragma unroll
                for (int mi = 0; mi < 2; mi++) {
#pragma unroll
                    for (int s = 0; s < 2; s++) {
                        mma16816h(acc[mi][2 * q + s], ah[mi], bh + 2 * s);
                    }
                }
            }
        }
        __syncthreads();
    }

    // epilogue: fp32 z1 + fused BN stats
    float* Sa = (float*)sm;
    float* Sq = (float*)(sm + 2048);
#pragma unroll
    for (int ni = 0; ni < 8; ni++) {
        int c0 = n0w + 8 * ni + 2 * (lane & 3);
        float s0 = 0.f, q0 = 0.f, s1 = 0.f, q1 = 0.f;
#pragma unroll
        for (int mi = 0; mi < 2; mi++) {
            int r0 = row0 + m0w + 16 * mi + (lane >> 2);
            int r1 = r0 + 8;
            float v0 = acc[mi][ni][0], v1 = acc[mi][ni][1];
            float v2 = acc[mi][ni][2], v3 = acc[mi][ni][3];
            if (r0 < NN) {
                *(float2*)(out + (long)r0 * DD + c0) = make_float2(v0, v1);
                s0 += v0; q0 = fmaf(v0, v0, q0);
                s1 += v1; q1 = fmaf(v1, v1, q1);
            }
            if (r1 < NN) {
                *(float2*)(out + (long)r1 * DD + c0) = make_float2(v2, v3);
                s0 += v2; q0 = fmaf(v2, v2, q0);
                s1 += v3; q1 = fmaf(v3, v3, q1);
            }
        }
#pragma unroll
        for (int m = 4; m <= 16; m <<= 1) {
            s0 += __shfl_xor_sync(0xffffffffu, s0, m);
            q0 += __shfl_xor_sync(0xffffffffu, q0, m);
            s1 += __shfl_xor_sync(0xffffffffu, s1, m);
            q1 += __shfl_xor_sync(0xffffffffu, q1, m);
        }
        if (lane < 4) {
            int cc = n0w + 8 * ni + 2 * lane;
            Sa[wm * 128 + cc] = s0; Sa[wm * 128 + cc + 1] = s1;
            Sq[wm * 128 + cc] = q0; Sq[wm * 128 + cc + 1] = q1;
        }
    }
    __syncthreads();
    if (t < 128) {
        float S = Sa[t] + Sa[128 + t] + Sa[256 + t] + Sa[384 + t];
        float Q = Sq[t] + Sq[128 + t] + Sq[256 + t] + Sq[384 + t];
        atomicAdd(&statsOut[t], S);
        atomicAdd(&statsOut[DD + t], Q);
    }
}

// ---------------- GEMM1: z2(fp16) = relu(BN1(z1)) @ W2 + b2, fused stats ----
__global__ void __launch_bounds__(256, 2)
k_gemm1(const float* __restrict__ P, const unsigned short* __restrict__ Wt,
        const float* __restrict__ bias,
        const float* __restrict__ g, const float* __restrict__ bt,
        const float* __restrict__ statsIn, float* __restrict__ statsOut,
        float* __restrict__ out) {
    __shared__ __align__(16) unsigned char sm[20480];
    unsigned sbase = smem_u32(sm);
    const unsigned WHI = 10240;

    int t = threadIdx.x;
    int lane = t & 31, wid = t >> 5;
    int wm = wid & 3, wn = wid >> 2;
    int m0w = wm * 32, n0w = wn * 64;
    int row0 = blockIdx.x * 128;
    int kc = (t & 7) << 2;

#pragma unroll
    for (int i = 0; i < 2; i++) {
        int id = t + i * 256;
        int n = id >> 2, q = id & 3;
        cpasync16(sbase + WHI + (unsigned)(n * 80 + q * 16), Wt + n * DD + q * 8);
    }
    asm volatile("cp.async.commit_group;");

    float4 pa[4];
#pragma unroll
    for (int i = 0; i < 4; i++) {
        int row = (t + i * 256) >> 3;
        int gr = row0 + row;
        pa[i] = (gr < NN) ? *(const float4*)(P + (long)gr * DD + kc)
                          : make_float4(0.f, 0.f, 0.f, 0.f);
    }

    float acc[2][8][4];
#pragma unroll
    for (int ni = 0; ni < 8; ni++) {
        int c0 = n0w + 8 * ni + 2 * (lane & 3);
        float b0 = bias[c0], b1 = bias[c0 + 1];
#pragma unroll
        for (int mi = 0; mi < 2; mi++) {
            acc[mi][ni][0] = b0; acc[mi][ni][1] = b1;
            acc[mi][ni][2] = b0; acc[mi][ni][3] = b1;
        }
    }

    for (int c = 0; c < 4; c++) {
        int kk = c * 32;
        float4 sc4, sh4;
        {
            int c0 = kk + kc;
            float4 smv = *(const float4*)(statsIn + c0);
            float4 sq = *(const float4*)(statsIn + DD + c0);
            float4 gv = *(const float4*)(g + c0);
            float4 bv = *(const float4*)(bt + c0);
            float mu, var, r;
            mu = smv.x * (1.f / NN); var = sq.x * (1.f / NN) - mu * mu;
            r = rsqrtf(var + 1e-5f); sc4.x = gv.x * r; sh4.x = fmaf(-mu, sc4.x, bv.x);
            mu = smv.y * (1.f / NN); var = sq.y * (1.f / NN) - mu * mu;
            r = rsqrtf(var + 1e-5f); sc4.y = gv.y * r; sh4.y = fmaf(-mu, sc4.y, bv.y);
            mu = smv.z * (1.f / NN); var = sq.z * (1.f / NN) - mu * mu;
            r = rsqrtf(var + 1e-5f); sc4.z = gv.z * r; sh4.z = fmaf(-mu, sc4.z, bv.z);
            mu = smv.w * (1.f / NN); var = sq.w * (1.f / NN) - mu * mu;
            r = rsqrtf(var + 1e-5f); sc4.w = gv.w * r; sh4.w = fmaf(-mu, sc4.w, bv.w);
        }

#pragma unroll
        for (int i = 0; i < 4; i++) {
            int row = (t + i * 256) >> 3;
            float4 v = pa[i];
            v.x = fmaxf(fmaf(v.x, sc4.x, sh4.x), 0.f);
            v.y = fmaxf(fmaf(v.y, sc4.y, sh4.y), 0.f);
            v.z = fmaxf(fmaf(v.z, sc4.z, sh4.z), 0.f);
            v.w = fmaxf(fmaf(v.w, sc4.w, sh4.w), 0.f);
            unsigned off = (unsigned)(row * 80 + kc * 2);
            *(unsigned*)(sm + off) = f2_to_h2(v.x, v.y);
            *(unsigned*)(sm + off + 4) = f2_to_h2(v.z, v.w);
        }

        if (c < 3) {
#pragma unroll
            for (int i = 0; i < 4; i++) {
                int row = (t + i * 256) >> 3;
                int gr = row0 + row;
                pa[i] = (gr < NN) ? *(const float4*)(P + (long)gr * DD + kk + 32 + kc)
                                  : make_float4(0.f, 0.f, 0.f, 0.f);
            }
        }

        asm volatile("cp.async.wait_group 0;");
        __syncthreads();

#pragma unroll
        for (int ks = 0; ks < 2; ks++) {
            int kb = ks * 16;
            unsigned ah[2][4];
#pragma unroll
            for (int mi = 0; mi < 2; mi++) {
                unsigned ad = sbase
                    + (unsigned)((m0w + 16 * mi + (lane & 7) + ((lane >> 3) & 1) * 8) * 80
                                 + (kb + (lane >> 4) * 8) * 2);
                ldsm4(ah[mi], ad);
            }
#pragma unroll
            for (int q = 0; q < 4; q++) {
                unsigned bd = sbase + WHI
                    + (unsigned)((n0w + 16 * q + ((lane >> 4) & 1) * 8 + (lane & 7)) * 80
                                 + (kb + ((lane >> 3) & 1) * 8) * 2);
                unsigned bh[4];
                ldsm4(bh, bd);
#pragma unroll
                for (int mi = 0; mi < 2; mi++) {
#pragma unroll
                    for (int s = 0; s < 2; s++) {
                        mma16816h(acc[mi][2 * q + s], ah[mi], bh + 2 * s);
                    }
                }
            }
        }
        __syncthreads();

        if (c < 3) {
#pragma unroll
            for (int i = 0; i < 2; i++) {
                int id = t + i * 256;
                int n = id >> 2, q = id & 3;
                cpasync16(sbase + WHI + (unsigned)(n * 80 + q * 16),
                          Wt + n * DD + (kk + 32) + q * 8);
            }
            asm volatile("cp.async.commit_group;");
        }
    }

    float* Sa = (float*)sm;
    float* Sq = (float*)(sm + 2048);
    unsigned short* outh = (unsigned short*)out;
#pragma unroll
    for (int ni = 0; ni < 8; ni++) {
        int c0 = n0w + 8 * ni + 2 * (lane & 3);
        float s0 = 0.f, q0 = 0.f, s1 = 0.f, q1 = 0.f;
#pragma unroll
        for (int mi = 0; mi < 2; mi++) {
            int r0 = row0 + m0w + 16 * mi + (lane >> 2);
            int r1 = r0 + 8;
            float v0 = acc[mi][ni][0], v1 = acc[mi][ni][1];
            float v2 = acc[mi][ni][2], v3 = acc[mi][ni][3];
            if (r0 < NN) {
                *(unsigned*)(outh + (long)r0 * DD + c0) = f2_to_h2(v0, v1);
                s0 += v0; q0 = fmaf(v0, v0, q0);
                s1 += v1; q1 = fmaf(v1, v1, q1);
            }
            if (r1 < NN) {
                *(unsigned*)(outh + (long)r1 * DD + c0) = f2_to_h2(v2, v3);
                s0 += v2; q0 = fmaf(v2, v2, q0);
                s1 += v3; q1 = fmaf(v3, v3, q1);
            }
        }
#pragma unroll
        for (int m = 4; m <= 16; m <<= 1) {
            s0 += __shfl_xor_sync(0xffffffffu, s0, m);
            q0 += __shfl_xor_sync(0xffffffffu, q0, m);
            s1 += __shfl_xor_sync(0xffffffffu, s1, m);
            q1 += __shfl_xor_sync(0xffffffffu, q1, m);
        }
        if (lane < 4) {
            int cc = n0w + 8 * ni + 2 * lane;
            Sa[wm * 128 + cc] = s0; Sa[wm * 128 + cc + 1] = s1;
            Sq[wm * 128 + cc] = q0; Sq[wm * 128 + cc + 1] = q1;
        }
    }
    __syncthreads();
    if (t < 128) {
        float S = Sa[t] + Sa[128 + t] + Sa[256 + t] + Sa[384 + t];
        float Q = Sq[t] + Sq[128 + t] + Sq[256 + t] + Sq[384 + t];
        atomicAdd(&statsOut[t], S);
        atomicAdd(&statsOut[DD + t], Q);
    }
}

// Final BN+ReLU: read fp16 z2, write fp16 h; merge readout runs (batch sorted).
__global__ void k_epilogue(const unsigned short* __restrict__ Z, const int* __restrict__ batch,
                           const float* __restrict__ g, const float* __restrict__ bt,
                           const float* __restrict__ statsIn, int layer) {
    __shared__ float esc[DD], esh[DD];
    __shared__ float zbuf[8][DD];
    __shared__ int bid[8];
    int t = threadIdx.x;
    int w = t >> 5, lane = t & 31;
    if (t < DD) {
        float mu = statsIn[t] * (1.f / NN);
        float var = statsIn[DD + t] * (1.f / NN) - mu * mu;
        float r = rsqrtf(var + 1e-5f);
        float sc = g[t] * r;
        esc[t] = sc;
        esh[t] = fmaf(-mu, sc, bt[t]);
    }
    __syncthreads();
    int node = blockIdx.x * 8 + w;
    int c4 = lane << 2;
    uint2 zh = *(const uint2*)(Z + (long)node * DD + c4);
    float2 p0 = h2f(zh.x), p1 = h2f(zh.y);
    float4 z = make_float4(p0.x, p0.y, p1.x, p1.y);
    z.x = fmaxf(fmaf(z.x, esc[c4 + 0], esh[c4 + 0]), 0.f);
    z.y = fmaxf(fmaf(z.y, esc[c4 + 1], esh[c4 + 1]), 0.f);
    z.z = fmaxf(fmaf(z.z, esc[c4 + 2], esh[c4 + 2]), 0.f);
    z.w = fmaxf(fmaf(z.w, esc[c4 + 3], esh[c4 + 3]), 0.f);
    *(uint2*)(d_Hb + (long)node * DD + c4) = f4_to_h4(z);
    *(float4*)&zbuf[w][c4] = z;
    if (lane == 0) bid[w] = d_is64 ? batch[2 * node] : batch[node];
    __syncthreads();
    int b = bid[w];
    bool leader = (w == 0) || (bid[w - 1] != b);
    if (leader) {
        float4 s = *(float4*)&zbuf[w][c4];
        for (int u = w + 1; u < 8 && bid[u] == b; u++) {
            float4 q = *(float4*)&zbuf[u][c4];
            s.x += q.x; s.y += q.y; s.z += q.z; s.w += q.w;
        }
        red4(d_readout + b * (NL * DD) + layer * DD + c4, s);
    }
}

__global__ void k_classifier(const float* __restrict__ Wc1, const float* __restrict__ bc1,
                             const float* __restrict__ Wc2, const float* __restrict__ bc2,
                             float* __restrict__ out) {
    int gidx = blockIdx.x;
    int t = threadIdx.x;
    __shared__ float red[NCLS];
    const float* r = d_readout + gidx * (NL * DD);
    float acc = bc1[t];
#pragma unroll 4
    for (int k = 0; k < NL * DD; k++) acc = fmaf(r[k], Wc1[k * DD + t], acc);
    float h = fmaxf(acc, 0.f);
    if (t < NCLS) red[t] = 0.f;
    __syncthreads();
#pragma unroll
    for (int c = 0; c < NCLS; c++) atomicAdd(&red[c], h * Wc2[t * NCLS + c]);
    __syncthreads();
    if (t < NCLS) out[gidx * NCLS + t] = red[t] + bc2[t];
}

// ---------------- launcher ----------------
extern "C" void kernel_launch(void* const* d_in, const int* in_sizes, int n_in,
                              void* d_out, int out_size) {
    const float* x   = (const float*)d_in[0];
    const int*   ei  = (const int*)d_in[1];
    const int*   bat = (const int*)d_in[2];
    const float* W1  = (const float*)d_in[3];
    const float* b1  = (const float*)d_in[4];
    const float* g1  = (const float*)d_in[5];
    const float* bt1 = (const float*)d_in[6];
    const float* W2  = (const float*)d_in[7];
    const float* b2  = (const float*)d_in[8];
    const float* g2  = (const float*)d_in[9];
    const float* bt2 = (const float*)d_in[10];
    const float* Wc1 = (const float*)d_in[11];
    const float* bc1 = (const float*)d_in[12];
    const float* Wc2 = (const float*)d_in[13];
    const float* bc2 = (const float*)d_in[14];
    float* out = (float*)d_out;

    float *pB, *pC, *pStats;
    unsigned short* pWt;
    cudaGetSymbolAddress((void**)&pB, d_B);
    cudaGetSymbolAddress((void**)&pC, d_C);
    cudaGetSymbolAddress((void**)&pStats, d_stats);
    cudaGetSymbolAddress((void**)&pWt, d_Wt);

    // one-time (first call is the uncaptured correctness run)
    static cudaStream_t sCSR = nullptr;
    static cudaEvent_t evFork = nullptr, evJoin = nullptr;
    if (!sCSR) {
        cudaStreamCreateWithFlags(&sCSR, cudaStreamNonBlocking);
        cudaEventCreateWithFlags(&evFork, cudaEventDisableTiming);
        cudaEventCreateWithFlags(&evJoin, cudaEventDisableTiming);
    }

    // setup: CSR chain on sCSR concurrent with prep on main
    cudaEventRecord(evFork, 0);
    cudaStreamWaitEvent(sCSR, evFork, 0);
    k_init<<<384, 256, 0, sCSR>>>(ei);
    k_hist<<<(NE + 255) / 256, 256, 0, sCSR>>>(ei);
    k_scan1<<<196, 256, 0, sCSR>>>();
    k_scan23<<<196, 256, 0, sCSR>>>();
    k_fill<<<(NE + 255) / 256, 256, 0, sCSR>>>(ei);
    cudaEventRecord(evJoin, sCSR);

    k_prep<<<6634, 256>>>(x, W1, W2);
    cudaStreamWaitEvent(0, evJoin, 0);   // join before the layer loop

    for (int L = 0; L < NL; L++) {
        float* s1 = pStats + (L * 2 + 0) * (2 * DD);
        float* s2 = pStats + (L * 2 + 1) * (2 * DD);
        k_agg<<<3125, 256>>>();
        k_gemm0<<<M_TILES, 256>>>((const unsigned short*)pB, pWt + L * 16384,
                                  b1 + L * DD, s1, pC);
        k_gemm1<<<M_TILES, 256>>>(pC, pWt + (3 + L) * 16384, b2 + L * DD,
                                  g1 + L * DD, bt1 + L * DD, s1, s2, pB);
        k_epilogue<<<NN / 8, 256>>>((unsigned short*)pB, bat,
                                    g2 + L * DD, bt2 + L * DD, s2, L);
    }
    k_classifier<<<NG, 128>>>(Wc1, bc1, Wc2, bc2, out);
}

// round 17
// speedup vs baseline: 1.4392x; 1.0197x over previous
#include <cuda_runtime.h>
#include <cuda_bf16.h>
#include <cuda_fp16.h>

#define NN 50000
#define NE 800000
#define DD 128
#define NL 3
#define NG 256
#define NCLS 10
#define M_TILES 391    // ceil(50000/128)
#define G1_BLOCKS 196  // gemm1 fused grid (<= guaranteed-resident 296)
#define G1_SMEM (20480 + 2 * 32768)   // pipeline + 2 z2 tiles = 86016

// ---------------- scratch (static device globals; no allocation) ----------------
__device__ unsigned short d_Hb[NN * DD];     // h as fp16 (gather format)
__device__ float d_B[NN * DD];               // agg (fp16 in low half)
__device__ float d_C[NN * DD];               // z1 (fp32)
__device__ float d_stats[NL * 2 * 2 * DD];   // per (layer, bn#): [sum | sumsq]
__device__ float d_readout[NG * NL * DD];
__device__ unsigned short d_Wt[6 * DD * DD]; // W transposed fp16: [mat][n][k]
__device__ unsigned d_cnt[NL];               // gemm1 barrier counters
__device__ int   d_deg[NN];
__device__ int   d_cur[NN];
__device__ int   d_off[NN + 1];
__device__ int   d_csr[NE];
__device__ int   d_bsum[256];
__device__ int   d_is64;

// ---------------- helpers ----------------
__device__ __forceinline__ void red4(float* p, float4 v) {
    asm volatile("red.global.add.v4.f32 [%0], {%1,%2,%3,%4};"
                 :: "l"(p), "f"(v.x), "f"(v.y), "f"(v.z), "f"(v.w) : "memory");
}
__device__ __forceinline__ unsigned smem_u32(const void* p) {
    unsigned r;
    asm("{ .reg .u64 t; cvta.to.shared.u64 t, %1; cvt.u32.u64 %0, t; }" : "=r"(r) : "l"(p));
    return r;
}
__device__ __forceinline__ void cpasync16(unsigned dst, const void* src) {
    asm volatile("cp.async.cg.shared.global [%0], [%1], 16;" :: "r"(dst), "l"(src));
}
__device__ __forceinline__ void mma16816h(float* d, const unsigned* a, const unsigned* b) {
    asm volatile("mma.sync.aligned.m16n8k16.row.col.f32.f16.f16.f32 "
                 "{%0,%1,%2,%3},{%4,%5,%6,%7},{%8,%9},{%0,%1,%2,%3};"
                 : "+f"(d[0]), "+f"(d[1]), "+f"(d[2]), "+f"(d[3])
                 : "r"(a[0]), "r"(a[1]), "r"(a[2]), "r"(a[3]), "r"(b[0]), "r"(b[1]));
}
__device__ __forceinline__ void ldsm4(unsigned* r, unsigned addr) {
    asm volatile("ldmatrix.sync.aligned.m8n8.x4.shared.b16 {%0,%1,%2,%3},[%4];"
                 : "=r"(r[0]), "=r"(r[1]), "=r"(r[2]), "=r"(r[3]) : "r"(addr));
}
__device__ __forceinline__ float2 h2f(unsigned u) {
    return __half22float2(*(__half2*)&u);
}
__device__ __forceinline__ unsigned f2_to_h2(float x, float y) {
    __half2 a = __floats2half2_rn(x, y);
    return *(unsigned*)&a;
}
__device__ __forceinline__ uint2 f4_to_h4(float4 v) {
    uint2 o; o.x = f2_to_h2(v.x, v.y); o.y = f2_to_h2(v.z, v.w);
    return o;
}
__device__ __forceinline__ void addrow(float4& a, uint2 v) {
    float2 p0 = h2f(v.x), p1 = h2f(v.y);
    a.x += p0.x; a.y += p0.y; a.z += p1.x; a.w += p1.y;
}

// ---------------- setup kernels ----------------

__global__ void k_init(const int* __restrict__ ei) {
    int i = blockIdx.x * 256 + threadIdx.x;
    if (i == 0) {
        int z = 1;
#pragma unroll
        for (int k = 1; k < 256; k += 2) z &= (ei[k] == 0);
        d_is64 = z;
    }
    if (i < NG * NL * DD) d_readout[i] = 0.f;
    if (i < NL * 2 * 2 * DD) d_stats[i] = 0.f;
    if (i < NL) d_cnt[i] = 0u;
    if (i < NN) d_deg[i] = 0;
}

// x -> fp16 Hb; W -> transposed fp16 planes
__global__ void k_prep(const float* __restrict__ x,
                       const float* __restrict__ W1, const float* __restrict__ W2) {
    if (blockIdx.x < 6250) {
        int i = blockIdx.x * 256 + threadIdx.x;      // NN*32 = 1.6M
        float4 v = ((const float4*)x)[i];
        ((uint2*)d_Hb)[i] = f4_to_h4(v);
    } else {
        int id = (blockIdx.x - 6250) * 256 + threadIdx.x;  // 6*16384
        int mat = id >> 14;
        int r = id & 16383;
        int n = r & 127, k = r >> 7;
        const float* src = (mat < 3) ? (W1 + mat * 16384) : (W2 + (mat - 3) * 16384);
        d_Wt[mat * 16384 + n * DD + k] =
            __half_as_ushort(__float2half_rn(src[k * DD + n]));
    }
}

__global__ void k_hist(const int* __restrict__ ei) {
    int e = blockIdx.x * 256 + threadIdx.x;
    if (e >= NE) return;
    int dst = d_is64 ? ei[2 * (NE + e)] : ei[NE + e];
    atomicAdd(&d_deg[dst], 1);
}

__global__ void k_scan1() {
    __shared__ int s[256];
    int t = threadIdx.x;
    int i = blockIdx.x * 256 + t;
    int v = (i < NN) ? d_deg[i] : 0;
    s[t] = v;
    __syncthreads();
#pragma unroll
    for (int d = 1; d < 256; d <<= 1) {
        int x = (t >= d) ? s[t - d] : 0;
        __syncthreads();
        s[t] += x;
        __syncthreads();
    }
    if (i < NN) d_off[i + 1] = s[t];
    if (t == 255) d_bsum[blockIdx.x] = s[255];
}

__global__ void k_scan23() {
    __shared__ int s[256];
    int t = threadIdx.x;
    s[t] = (t < 196) ? d_bsum[t] : 0;
    __syncthreads();
#pragma unroll
    for (int d = 1; d < 256; d <<= 1) {
        int x = (t >= d) ? s[t - d] : 0;
        __syncthreads();
        s[t] += x;
        __syncthreads();
    }
    int b = blockIdx.x;
    int pre = (b == 0) ? 0 : s[b - 1];
    int i = b * 256 + t;
    if (i < NN) { d_off[i + 1] += pre; d_cur[i] = 0; }
    if (i == 0) d_off[0] = 0;
}

__global__ void k_fill(const int* __restrict__ ei) {
    int e = blockIdx.x * 256 + threadIdx.x;
    if (e >= NE) return;
    int src, dst;
    if (d_is64) { src = ei[2 * e]; dst = ei[2 * (NE + e)]; }
    else        { src = ei[e];     dst = ei[NE + e]; }
    int p = atomicAdd(&d_cur[dst], 1);
    d_csr[d_off[dst] + p] = src;
}

// One warp per TWO nodes: full-warp uint2 gather; OUTPUT fp16 (coalesced uint2).
__global__ void k_agg() {
    int w = (blockIdx.x * 256 + threadIdx.x) >> 5;
    int n0 = 2 * w, n1 = 2 * w + 1;
    if (n0 >= NN) return;
    int lane = threadIdx.x & 31;
    const uint2* hv = (const uint2*)d_Hb;
    float4 aA, aB;
    { uint2 v = __ldg(&hv[(long)n0 * 32 + lane]); float2 p0 = h2f(v.x), p1 = h2f(v.y);
      aA = make_float4(p0.x, p0.y, p1.x, p1.y); }
    { uint2 v = __ldg(&hv[(long)n1 * 32 + lane]); float2 p0 = h2f(v.x), p1 = h2f(v.y);
      aB = make_float4(p0.x, p0.y, p1.x, p1.y); }
    int j0 = d_off[n0], e0 = d_off[n0 + 1];
    int j1 = e0,        e1 = d_off[n1 + 1];
    while (j0 + 4 <= e0 && j1 + 4 <= e1) {
        int s00 = d_csr[j0], s01 = d_csr[j0 + 1], s02 = d_csr[j0 + 2], s03 = d_csr[j0 + 3];
        int s10 = d_csr[j1], s11 = d_csr[j1 + 1], s12 = d_csr[j1 + 2], s13 = d_csr[j1 + 3];
        uint2 v00 = __ldg(&hv[(long)s00 * 32 + lane]);
        uint2 v01 = __ldg(&hv[(long)s01 * 32 + lane]);
        uint2 v02 = __ldg(&hv[(long)s02 * 32 + lane]);
        uint2 v03 = __ldg(&hv[(long)s03 * 32 + lane]);
        uint2 v10 = __ldg(&hv[(long)s10 * 32 + lane]);
        uint2 v11 = __ldg(&hv[(long)s11 * 32 + lane]);
        uint2 v12 = __ldg(&hv[(long)s12 * 32 + lane]);
        uint2 v13 = __ldg(&hv[(long)s13 * 32 + lane]);
        addrow(aA, v00); addrow(aA, v01); addrow(aA, v02); addrow(aA, v03);
        addrow(aB, v10); addrow(aB, v11); addrow(aB, v12); addrow(aB, v13);
        j0 += 4; j1 += 4;
    }
    for (; j0 + 4 <= e0; j0 += 4) {
        int s0 = d_csr[j0], s1 = d_csr[j0 + 1], s2 = d_csr[j0 + 2], s3 = d_csr[j0 + 3];
        uint2 v0 = __ldg(&hv[(long)s0 * 32 + lane]);
        uint2 v1 = __ldg(&hv[(long)s1 * 32 + lane]);
        uint2 v2 = __ldg(&hv[(long)s2 * 32 + lane]);
        uint2 v3 = __ldg(&hv[(long)s3 * 32 + lane]);
        addrow(aA, v0); addrow(aA, v1); addrow(aA, v2); addrow(aA, v3);
    }
    for (; j0 < e0; j0++) addrow(aA, __ldg(&hv[(long)d_csr[j0] * 32 + lane]));
    for (; j1 + 4 <= e1; j1 += 4) {
        int s0 = d_csr[j1], s1 = d_csr[j1 + 1], s2 = d_csr[j1 + 2], s3 = d_csr[j1 + 3];
        uint2 v0 = __ldg(&hv[(long)s0 * 32 + lane]);
        uint2 v1 = __ldg(&hv[(long)s1 * 32 + lane]);
        uint2 v2 = __ldg(&hv[(long)s2 * 32 + lane]);
        uint2 v3 = __ldg(&hv[(long)s3 * 32 + lane]);
        addrow(aB, v0); addrow(aB, v1); addrow(aB, v2); addrow(aB, v3);
    }
    for (; j1 < e1; j1++) addrow(aB, __ldg(&hv[(long)d_csr[j1] * 32 + lane]));
    ((uint2*)d_B)[(long)n0 * 32 + lane] = f4_to_h4(aA);
    ((uint2*)d_B)[(long)n1 * 32 + lane] = f4_to_h4(aB);
}

// ---------------- GEMM0: z1 = agg(fp16) @ W1 + b1, fused BN stats -----------
__global__ void __launch_bounds__(256, 2)
k_gemm0(const unsigned short* __restrict__ A, const unsigned short* __restrict__ Wt,
        const float* __restrict__ bias, float* __restrict__ statsOut,
        float* __restrict__ out) {
    __shared__ __align__(16) unsigned char sm[40960];
    unsigned sbase = smem_u32(sm);

    int t = threadIdx.x;
    int lane = t & 31, wid = t >> 5;
    int wm = wid & 3, wn = wid >> 2;
    int m0w = wm * 32, n0w = wn * 64;
    int row0 = blockIdx.x * 128;

    {
        unsigned ab = sbase, wb = sbase + 20480u;
#pragma unroll
        for (int i = 0; i < 2; i++) {
            int id = t + i * 256;
            int r = id >> 2, q = id & 3;
            cpasync16(ab + (unsigned)(r * 80 + q * 16), A + (long)(row0 + r) * DD + q * 8);
            cpasync16(wb + (unsigned)(r * 80 + q * 16), Wt + r * DD + q * 8);
        }
        asm volatile("cp.async.commit_group;");
    }

    float acc[2][8][4];
#pragma unroll
    for (int ni = 0; ni < 8; ni++) {
        int c0 = n0w + 8 * ni + 2 * (lane & 3);
        float b0 = bias[c0], b1 = bias[c0 + 1];
#pragma unroll
        for (int mi = 0; mi < 2; mi++) {
            acc[mi][ni][0] = b0; acc[mi][ni][1] = b1;
            acc[mi][ni][2] = b0; acc[mi][ni][3] = b1;
        }
    }

    for (int c = 0; c < 4; c++) {
        if (c < 3) {
            int nb = (c + 1) & 1;
            unsigned ab = sbase + nb * 10240u, wb = sbase + 20480u + nb * 10240u;
            int kk2 = (c + 1) * 32;
#pragma unroll
            for (int i = 0; i < 2; i++) {
                int id = t + i * 256;
                int r = id >> 2, q = id & 3;
                cpasync16(ab + (unsigned)(r * 80 + q * 16),
                          A + (long)(row0 + r) * DD + kk2 + q * 8);
                cpasync16(wb + (unsigned)(r * 80 + q * 16), Wt + r * DD + kk2 + q * 8);
            }
            asm volatile("cp.async.commit_group;");
            asm volatile("cp.async.wait_group 1;");
        } else {
            asm volatile("cp.async.wait_group 0;");
        }
        __syncthreads();

        unsigned abase = sbase + (c & 1) * 10240u;
        unsigned wbase = sbase + 20480u + (c & 1) * 10240u;
#pragma unroll
        for (int ks = 0; ks < 2; ks++) {
            int kb = ks * 16;
            unsigned ah[2][4];
#pragma unroll
            for (int mi = 0; mi < 2; mi++) {
                unsigned ad = abase
                    + (unsigned)((m0w + 16 * mi + (lane & 7) + ((lane >> 3) & 1) * 8) * 80
                                 + (kb + (lane >> 4) * 8) * 2);
                ldsm4(ah[mi], ad);
            }
#pragma unroll
            for (int q = 0; q < 4; q++) {
                unsigned bd = wbase
                    + (unsigned)((n0w + 16 * q + ((lane >> 4) & 1) * 8 + (lane & 7)) * 80
                                 + (kb + ((lane >> 3) & 1) * 8) * 2);
                unsigned bh[4];
                ldsm4(bh, bd);
#pragma unroll
                for (int mi = 0; mi < 2; mi++) {
#pragma unroll
                    for (int s = 0; s < 2; s++) {
                        mma16816h(acc[mi][2 * q + s], ah[mi], bh + 2 * s);
                    }
                }
            }
        }
        __syncthreads();
    }

    float* Sa = (float*)sm;
    float* Sq = (float*)(sm + 2048);
#pragma unroll
    for (int ni = 0; ni < 8; ni++) {
        int c0 = n0w + 8 * ni + 2 * (lane & 3);
        float s0 = 0.f, q0 = 0.f, s1 = 0.f, q1 = 0.f;
#pragma unroll
        for (int mi = 0; mi < 2; mi++) {
            int r0 = row0 + m0w + 16 * mi + (lane >> 2);
            int r1 = r0 + 8;
            float v0 = acc[mi][ni][0], v1 = acc[mi][ni][1];
            float v2 = acc[mi][ni][2], v3 = acc[mi][ni][3];
            if (r0 < NN) {
                *(float2*)(out + (long)r0 * DD + c0) = make_float2(v0, v1);
                s0 += v0; q0 = fmaf(v0, v0, q0);
                s1 += v1; q1 = fmaf(v1, v1, q1);
            }
            if (r1 < NN) {
                *(float2*)(out + (long)r1 * DD + c0) = make_float2(v2, v3);
                s0 += v2; q0 = fmaf(v2, v2, q0);
                s1 += v3; q1 = fmaf(v3, v3, q1);
            }
        }
#pragma unroll
        for (int m = 4; m <= 16; m <<= 1) {
            s0 += __shfl_xor_sync(0xffffffffu, s0, m);
            q0 += __shfl_xor_sync(0xffffffffu, q0, m);
            s1 += __shfl_xor_sync(0xffffffffu, s1, m);
            q1 += __shfl_xor_sync(0xffffffffu, q1, m);
        }
        if (lane < 4) {
            int cc = n0w + 8 * ni + 2 * lane;
            Sa[wm * 128 + cc] = s0; Sa[wm * 128 + cc + 1] = s1;
            Sq[wm * 128 + cc] = q0; Sq[wm * 128 + cc + 1] = q1;
        }
    }
    __syncthreads();
    if (t < 128) {
        float S = Sa[t] + Sa[128 + t] + Sa[256 + t] + Sa[384 + t];
        float Q = Sq[t] + Sq[128 + t] + Sq[256 + t] + Sq[384 + t];
        atomicAdd(&statsOut[t], S);
        atomicAdd(&statsOut[DD + t], Q);
    }
}

// ---------------- GEMM1 FUSED: z2 + BN2 stats + global barrier + BN2/ReLU/h/readout
// 196 blocks x 2 tiles. z2 spilled to smem (fp16); no global z2 traffic, no epilogue kernel.
extern __shared__ unsigned char dsm[];

__global__ void __launch_bounds__(256, 2)
k_gemm1f(const float* __restrict__ P, const unsigned short* __restrict__ Wt,
         const float* __restrict__ bias,
         const float* __restrict__ g1v, const float* __restrict__ bt1v,
         const float* __restrict__ g2v, const float* __restrict__ bt2v,
         const float* __restrict__ statsIn, float* __restrict__ statsOut,
         const int* __restrict__ batch, int layer) {
    unsigned sbase = smem_u32(dsm);
    const unsigned WHI = 10240;
    __shared__ float esc[DD], esh[DD];

    int t = threadIdx.x;
    int lane = t & 31, wid = t >> 5;
    int wm = wid & 3, wn = wid >> 2;
    int m0w = wm * 32, n0w = wn * 64;
    int kc = (t & 7) << 2;

    // ================= phase 1: MMA + stats per owned tile =================
    for (int ti = 0; ti < 2; ti++) {
        int tile = blockIdx.x + ti * G1_BLOCKS;
        int row0 = tile * 128;
        if (row0 >= NN) break;
        unsigned short* z2s = (unsigned short*)(dsm + 20480 + ti * 32768);

        // W chunk0
#pragma unroll
        for (int i = 0; i < 2; i++) {
            int id = t + i * 256;
            int n = id >> 2, q = id & 3;
            cpasync16(sbase + WHI + (unsigned)(n * 80 + q * 16), Wt + n * DD + q * 8);
        }
        asm volatile("cp.async.commit_group;");

        float4 pa[4];
#pragma unroll
        for (int i = 0; i < 4; i++) {
            int row = (t + i * 256) >> 3;
            int gr = row0 + row;
            pa[i] = (gr < NN) ? *(const float4*)(P + (long)gr * DD + kc)
                              : make_float4(0.f, 0.f, 0.f, 0.f);
        }

        float acc[2][8][4];
#pragma unroll
        for (int ni = 0; ni < 8; ni++) {
            int c0 = n0w + 8 * ni + 2 * (lane & 3);
            float b0 = bias[c0], b1 = bias[c0 + 1];
#pragma unroll
            for (int mi = 0; mi < 2; mi++) {
                acc[mi][ni][0] = b0; acc[mi][ni][1] = b1;
                acc[mi][ni][2] = b0; acc[mi][ni][3] = b1;
            }
        }

        for (int c = 0; c < 4; c++) {
            int kk = c * 32;
            float4 sc4, sh4;
            {
                int c0 = kk + kc;
                float4 smv = *(const float4*)(statsIn + c0);
                float4 sq = *(const float4*)(statsIn + DD + c0);
                float4 gv = *(const float4*)(g1v + c0);
                float4 bv = *(const float4*)(bt1v + c0);
                float mu, var, r;
                mu = smv.x * (1.f / NN); var = sq.x * (1.f / NN) - mu * mu;
                r = rsqrtf(var + 1e-5f); sc4.x = gv.x * r; sh4.x = fmaf(-mu, sc4.x, bv.x);
                mu = smv.y * (1.f / NN); var = sq.y * (1.f / NN) - mu * mu;
                r = rsqrtf(var + 1e-5f); sc4.y = gv.y * r; sh4.y = fmaf(-mu, sc4.y, bv.y);
                mu = smv.z * (1.f / NN); var = sq.z * (1.f / NN) - mu * mu;
                r = rsqrtf(var + 1e-5f); sc4.z = gv.z * r; sh4.z = fmaf(-mu, sc4.z, bv.z);
                mu = smv.w * (1.f / NN); var = sq.w * (1.f / NN) - mu * mu;
                r = rsqrtf(var + 1e-5f); sc4.w = gv.w * r; sh4.w = fmaf(-mu, sc4.w, bv.w);
            }

#pragma unroll
            for (int i = 0; i < 4; i++) {
                int row = (t + i * 256) >> 3;
                float4 v = pa[i];
                v.x = fmaxf(fmaf(v.x, sc4.x, sh4.x), 0.f);
                v.y = fmaxf(fmaf(v.y, sc4.y, sh4.y), 0.f);
                v.z = fmaxf(fmaf(v.z, sc4.z, sh4.z), 0.f);
                v.w = fmaxf(fmaf(v.w, sc4.w, sh4.w), 0.f);
                unsigned off = (unsigned)(row * 80 + kc * 2);
                *(unsigned*)(dsm + off) = f2_to_h2(v.x, v.y);
                *(unsigned*)(dsm + off + 4) = f2_to_h2(v.z, v.w);
            }

            if (c < 3) {
#pragma unroll
                for (int i = 0; i < 4; i++) {
                    int row = (t + i * 256) >> 3;
                    int gr = row0 + row;
                    pa[i] = (gr < NN) ? *(const float4*)(P + (long)gr * DD + kk + 32 + kc)
                                      : make_float4(0.f, 0.f, 0.f, 0.f);
                }
            }

            asm volatile("cp.async.wait_group 0;");
            __syncthreads();

#pragma unroll
            for (int ks = 0; ks < 2; ks++) {
                int kb = ks * 16;
                unsigned ah[2][4];
#pragma unroll
                for (int mi = 0; mi < 2; mi++) {
                    unsigned ad = sbase
                        + (unsigned)((m0w + 16 * mi + (lane & 7) + ((lane >> 3) & 1) * 8) * 80
                                     + (kb + (lane >> 4) * 8) * 2);
                    ldsm4(ah[mi], ad);
                }
#pragma unroll
                for (int q = 0; q < 4; q++) {
                    unsigned bd = sbase + WHI
                        + (unsigned)((n0w + 16 * q + ((lane >> 4) & 1) * 8 + (lane & 7)) * 80
                                     + (kb + ((lane >> 3) & 1) * 8) * 2);
                    unsigned bh[4];
                    ldsm4(bh, bd);
#pragma unroll
                    for (int mi = 0; mi < 2; mi++) {
#pragma unroll
                        for (int s = 0; s < 2; s++) {
                            mma16816h(acc[mi][2 * q + s], ah[mi], bh + 2 * s);
                        }
                    }
                }
            }
            __syncthreads();

            if (c < 3) {
#pragma unroll
                for (int i = 0; i < 2; i++) {
                    int id = t + i * 256;
                    int n = id >> 2, q = id & 3;
                    cpasync16(sbase + WHI + (unsigned)(n * 80 + q * 16),
                              Wt + n * DD + (kk + 32) + q * 8);
                }
                asm volatile("cp.async.commit_group;");
            }
        }

        // z2 -> smem (fp16) + stats
        float* Sa = (float*)dsm;
        float* Sq = (float*)(dsm + 2048);
#pragma unroll
        for (int ni = 0; ni < 8; ni++) {
            int c0 = n0w + 8 * ni + 2 * (lane & 3);
            float s0 = 0.f, q0 = 0.f, s1 = 0.f, q1 = 0.f;
#pragma unroll
            for (int mi = 0; mi < 2; mi++) {
                int rl0 = m0w + 16 * mi + (lane >> 2);
                int rl1 = rl0 + 8;
                float v0 = acc[mi][ni][0], v1 = acc[mi][ni][1];
                float v2 = acc[mi][ni][2], v3 = acc[mi][ni][3];
                *(unsigned*)(z2s + rl0 * DD + c0) = f2_to_h2(v0, v1);
                *(unsigned*)(z2s + rl1 * DD + c0) = f2_to_h2(v2, v3);
                if (row0 + rl0 < NN) {
                    s0 += v0; q0 = fmaf(v0, v0, q0);
                    s1 += v1; q1 = fmaf(v1, v1, q1);
                }
                if (row0 + rl1 < NN) {
                    s0 += v2; q0 = fmaf(v2, v2, q0);
                    s1 += v3; q1 = fmaf(v3, v3, q1);
                }
            }
#pragma unroll
            for (int m = 4; m <= 16; m <<= 1) {
                s0 += __shfl_xor_sync(0xffffffffu, s0, m);
                q0 += __shfl_xor_sync(0xffffffffu, q0, m);
                s1 += __shfl_xor_sync(0xffffffffu, s1, m);
                q1 += __shfl_xor_sync(0xffffffffu, q1, m);
            }
            if (lane < 4) {
                int cc = n0w + 8 * ni + 2 * lane;
                Sa[wm * 128 + cc] = s0; Sa[wm * 128 + cc + 1] = s1;
                Sq[wm * 128 + cc] = q0; Sq[wm * 128 + cc + 1] = q1;
            }
        }
        __syncthreads();
        if (t < 128) {
            float S = Sa[t] + Sa[128 + t] + Sa[256 + t] + Sa[384 + t];
            float Q = Sq[t] + Sq[128 + t] + Sq[256 + t] + Sq[384 + t];
            atomicAdd(&statsOut[t], S);
            atomicAdd(&statsOut[DD + t], Q);
        }
        __syncthreads();   // protect Sa/Sq + pipeline smem before next tile
    }

    // ================= global barrier =================
    __threadfence();
    __syncthreads();
    if (t == 0) {
        atomicAdd(&d_cnt[layer], 1u);
        while (atomicAdd(&d_cnt[layer], 0u) < (unsigned)G1_BLOCKS) __nanosleep(64);
    }
    __syncthreads();

    // ================= phase 2: BN2 affine + ReLU + h write + readout =======
    if (t < DD) {
        float mu = statsOut[t] * (1.f / NN);
        float var = statsOut[DD + t] * (1.f / NN) - mu * mu;
        float r = rsqrtf(var + 1e-5f);
        float sc = g2v[t] * r;
        esc[t] = sc;
        esh[t] = fmaf(-mu, sc, bt2v[t]);
    }
    __syncthreads();

    int is64 = d_is64;
    int c4 = lane * 4;
    for (int ti = 0; ti < 2; ti++) {
        int tile = blockIdx.x + ti * G1_BLOCKS;
        int row0 = tile * 128;
        if (row0 >= NN) break;
        const unsigned short* z2s = (const unsigned short*)(dsm + 20480 + ti * 32768);
        float4 run = make_float4(0.f, 0.f, 0.f, 0.f);
        int runb = -1;
        for (int r = wid * 16; r < wid * 16 + 16; r++) {
            int node = row0 + r;
            if (node >= NN) break;
            uint2 zz = *(const uint2*)(z2s + r * DD + c4);
            float2 p0 = h2f(zz.x), p1 = h2f(zz.y);
            float4 z = make_float4(p0.x, p0.y, p1.x, p1.y);
            z.x = fmaxf(fmaf(z.x, esc[c4 + 0], esh[c4 + 0]), 0.f);
            z.y = fmaxf(fmaf(z.y, esc[c4 + 1], esh[c4 + 1]), 0.f);
            z.z = fmaxf(fmaf(z.z, esc[c4 + 2], esh[c4 + 2]), 0.f);
            z.w = fmaxf(fmaf(z.w, esc[c4 + 3], esh[c4 + 3]), 0.f);
            *(uint2*)(d_Hb + (long)node * DD + c4) = f4_to_h4(z);
            int b = is64 ? batch[2 * node] : batch[node];
            if (b != runb) {
                if (runb >= 0)
                    red4(d_readout + runb * (NL * DD) + layer * DD + c4, run);
                runb = b;
                run = z;
            } else {
                run.x += z.x; run.y += z.y; run.z += z.z; run.w += z.w;
            }
        }
        if (runb >= 0)
            red4(d_readout + runb * (NL * DD) + layer * DD + c4, run);
    }
}

__global__ void k_classifier(const float* __restrict__ Wc1, const float* __restrict__ bc1,
                             const float* __restrict__ Wc2, const float* __restrict__ bc2,
                             float* __restrict__ out) {
    int gidx = blockIdx.x;
    int t = threadIdx.x;
    __shared__ float red[NCLS];
    const float* r = d_readout + gidx * (NL * DD);
    float acc = bc1[t];
#pragma unroll 4
    for (int k = 0; k < NL * DD; k++) acc = fmaf(r[k], Wc1[k * DD + t], acc);
    float h = fmaxf(acc, 0.f);
    if (t < NCLS) red[t] = 0.f;
    __syncthreads();
#pragma unroll
    for (int c = 0; c < NCLS; c++) atomicAdd(&red[c], h * Wc2[t * NCLS + c]);
    __syncthreads();
    if (t < NCLS) out[gidx * NCLS + t] = red[t] + bc2[t];
}

// ---------------- launcher ----------------
extern "C" void kernel_launch(void* const* d_in, const int* in_sizes, int n_in,
                              void* d_out, int out_size) {
    const float* x   = (const float*)d_in[0];
    const int*   ei  = (const int*)d_in[1];
    const int*   bat = (const int*)d_in[2];
    const float* W1  = (const float*)d_in[3];
    const float* b1  = (const float*)d_in[4];
    const float* g1  = (const float*)d_in[5];
    const float* bt1 = (const float*)d_in[6];
    const float* W2  = (const float*)d_in[7];
    const float* b2  = (const float*)d_in[8];
    const float* g2  = (const float*)d_in[9];
    const float* bt2 = (const float*)d_in[10];
    const float* Wc1 = (const float*)d_in[11];
    const float* bc1 = (const float*)d_in[12];
    const float* Wc2 = (const float*)d_in[13];
    const float* bc2 = (const float*)d_in[14];
    float* out = (float*)d_out;

    float *pB, *pC, *pStats;
    unsigned short* pWt;
    cudaGetSymbolAddress((void**)&pB, d_B);
    cudaGetSymbolAddress((void**)&pC, d_C);
    cudaGetSymbolAddress((void**)&pStats, d_stats);
    cudaGetSymbolAddress((void**)&pWt, d_Wt);

    // one-time (first call is the uncaptured correctness run)
    static cudaStream_t sCSR = nullptr;
    static cudaEvent_t evFork = nullptr, evJoin = nullptr;
    if (!sCSR) {
        cudaStreamCreateWithFlags(&sCSR, cudaStreamNonBlocking);
        cudaEventCreateWithFlags(&evFork, cudaEventDisableTiming);
        cudaEventCreateWithFlags(&evJoin, cudaEventDisableTiming);
        cudaFuncSetAttribute(k_gemm1f, cudaFuncAttributeMaxDynamicSharedMemorySize, G1_SMEM);
    }

    // setup: CSR chain on sCSR concurrent with prep on main
    cudaEventRecord(evFork, 0);
    cudaStreamWaitEvent(sCSR, evFork, 0);
    k_init<<<384, 256, 0, sCSR>>>(ei);
    k_hist<<<(NE + 255) / 256, 256, 0, sCSR>>>(ei);
    k_scan1<<<196, 256, 0, sCSR>>>();
    k_scan23<<<196, 256, 0, sCSR>>>();
    k_fill<<<(NE + 255) / 256, 256, 0, sCSR>>>(ei);
    cudaEventRecord(evJoin, sCSR);

    k_prep<<<6634, 256>>>(x, W1, W2);
    cudaStreamWaitEvent(0, evJoin, 0);   // join before the layer loop

    for (int L = 0; L < NL; L++) {
        float* s1 = pStats + (L * 2 + 0) * (2 * DD);
        float* s2 = pStats + (L * 2 + 1) * (2 * DD);
        k_agg<<<3125, 256>>>();
        k_gemm0<<<M_TILES, 256>>>((const unsigned short*)pB, pWt + L * 16384,
                                  b1 + L * DD, s1, pC);
        k_gemm1f<<<G1_BLOCKS, 256, G1_SMEM>>>(pC, pWt + (3 + L) * 16384, b2 + L * DD,
                                              g1 + L * DD, bt1 + L * DD,
                                              g2 + L * DD, bt2 + L * DD,
                                              s1, s2, bat, L);
    }
    k_classifier<<<NG, 128>>>(Wc1, bc1, Wc2, bc2, out);
}